// round 1
// baseline (speedup 1.0000x reference)
#include <cuda_runtime.h>
#include <cuda_bf16.h>
#include <math.h>

// ---------------- Problem constants ----------------
#define BATCH   4
#define HH      256
#define WW      256
#define HW      65536           // 256*256
#define CC      180
#define C1      60              // dim/3
#define CA      6               // dim/30
#define FF      720             // 4*dim
#define HEADS   6
#define HD      30
#define NTOK    262144          // BATCH*HW
// windows
#define NWIN    4096            // 4 * 32 * 32

// ---------------- Scratch (static device globals; no allocs) ----------------
__device__ float g_xn  [NTOK * CC];   // LN1 out, later LN2 out (reused)
__device__ float g_c1  [NTOK * C1];   // conv1 out (post-GELU)
__device__ float g_y   [NTOK * CC];   // conv2 out
__device__ float g_att [NTOK * CC];   // attention pre-proj out
__device__ float g_xmid[NTOK * CC];   // x + attn + conv branch
__device__ float g_h   [NTOK * FF];   // fc1 out
__device__ float g_poolp[BATCH * 32 * CC];
__device__ float g_a   [BATCH * CC];  // sigmoid(channel attn) * 0.01

__device__ __forceinline__ float gelu_f(float x) {
    return 0.5f * x * (1.0f + erff(x * 0.70710678118654752f));
}

// ---------------- LayerNorm (one warp per token) ----------------
__global__ void ln_kernel(const float* __restrict__ in, const float* __restrict__ g,
                          const float* __restrict__ bt, float* __restrict__ out, int ntok) {
    int gwarp = (blockIdx.x * blockDim.x + threadIdx.x) >> 5;
    int lane  = threadIdx.x & 31;
    if (gwarp >= ntok) return;
    const float* p = in + (size_t)gwarp * CC;
    float v[6];
    float s = 0.f, s2 = 0.f;
#pragma unroll
    for (int k = 0; k < 6; k++) {
        int c = lane + 32 * k;
        float xv = (c < CC) ? p[c] : 0.f;
        v[k] = xv; s += xv; s2 += xv * xv;
    }
#pragma unroll
    for (int o = 16; o > 0; o >>= 1) {
        s  += __shfl_xor_sync(0xffffffffu, s,  o);
        s2 += __shfl_xor_sync(0xffffffffu, s2, o);
    }
    float mean = s * (1.f / CC);
    float var  = s2 * (1.f / CC) - mean * mean;
    float inv  = rsqrtf(var + 1e-5f);
    float* q = out + (size_t)gwarp * CC;
#pragma unroll
    for (int k = 0; k < 6; k++) {
        int c = lane + 32 * k;
        if (c < CC) q[c] = (v[k] - mean) * inv * g[c] + bt[c];
    }
}

// ---------------- conv1: NHWC 3x3, 180 -> 60, + bias + GELU ----------------
// 16x16 pixel tile per block, 256 threads (1 px each), acc[60], ic chunks of 20.
#define C1_ICC 20
#define C1_ICP 21
__global__ __launch_bounds__(256, 2)
void conv1_kernel(const float* __restrict__ xn, const float* __restrict__ w1,
                  const float* __restrict__ b1, float* __restrict__ out) {
    extern __shared__ float sm[];
    float* sIn = sm;                 // [18*18][21]
    float* sW  = sm + 324 * C1_ICP;  // [20][60*9]
    const int tid = threadIdx.x;
    const int b  = blockIdx.z;
    const int h0 = blockIdx.y * 16, w0 = blockIdx.x * 16;
    const int pr = tid >> 4, pc = tid & 15;

    float acc[60];
#pragma unroll
    for (int o = 0; o < 60; o++) acc[o] = 0.f;

    for (int ic0 = 0; ic0 < CC; ic0 += C1_ICC) {
        __syncthreads();
        for (int idx = tid; idx < 324 * C1_ICC; idx += 256) {
            int icl = idx % C1_ICC;
            int sp  = idx / C1_ICC;
            int r = sp / 18, cc = sp % 18;
            int gh = h0 + r - 1, gw = w0 + cc - 1;
            float v = 0.f;
            if ((unsigned)gh < 256u && (unsigned)gw < 256u)
                v = xn[((size_t)(b * HW + gh * 256 + gw)) * CC + ic0 + icl];
            sIn[sp * C1_ICP + icl] = v;
        }
        for (int idx = tid; idx < C1_ICC * 540; idx += 256) {
            int k   = idx % 9;
            int oc  = (idx / 9) % 60;
            int icl = idx / 540;
            sW[icl * 540 + oc * 9 + k] = w1[((size_t)(oc * CC + ic0 + icl)) * 9 + k];
        }
        __syncthreads();
        for (int icl = 0; icl < C1_ICC; icl++) {
            float xv[9];
#pragma unroll
            for (int dr = 0; dr < 3; dr++)
#pragma unroll
                for (int dc = 0; dc < 3; dc++)
                    xv[dr * 3 + dc] = sIn[((pr + dr) * 18 + pc + dc) * C1_ICP + icl];
            const float* wp = sW + icl * 540;
#pragma unroll
            for (int o = 0; o < 60; o++) {
#pragma unroll
                for (int k = 0; k < 9; k++) acc[o] += xv[k] * wp[o * 9 + k];
            }
        }
    }
    __syncthreads();
    // stage through smem for coalesced stores; apply bias + GELU
    float* sOut = sm;  // [256][61] = 15616 floats, fits in 17604-float region
#pragma unroll
    for (int o = 0; o < 60; o++) sOut[tid * 61 + o] = gelu_f(acc[o] + b1[o]);
    __syncthreads();
    for (int idx = tid; idx < 256 * 60; idx += 256) {
        int px = idx / 60, oc = idx % 60;
        int gh = h0 + (px >> 4), gw = w0 + (px & 15);
        out[((size_t)(b * HW + gh * 256 + gw)) * C1 + oc] = sOut[px * 61 + oc];
    }
}

// ---------------- conv2: NHWC 3x3, 60 -> 180, + bias ----------------
// 16x16 pixel tile, 512 threads: thread = (px, half-of-oc), acc[90], ic chunks of 10.
#define C2_ICC 10
#define C2_ICP 11
__global__ __launch_bounds__(512, 1)
void conv2_kernel(const float* __restrict__ cin, const float* __restrict__ w2,
                  const float* __restrict__ b2, float* __restrict__ out) {
    extern __shared__ float sm[];
    float* sIn = sm;                  // [18*18][11]
    float* sW  = sm + 324 * C2_ICP;   // [10][180*9]
    const int tid = threadIdx.x;
    const int b  = blockIdx.z;
    const int h0 = blockIdx.y * 16, w0 = blockIdx.x * 16;
    const int px = tid & 255;
    const int gsel = tid >> 8;        // 0 or 1
    const int pr = px >> 4, pc = px & 15;
    const int oc0 = gsel * 90;

    float acc[90];
#pragma unroll
    for (int j = 0; j < 90; j++) acc[j] = 0.f;

    for (int ic0 = 0; ic0 < C1; ic0 += C2_ICC) {
        __syncthreads();
        for (int idx = tid; idx < 324 * C2_ICC; idx += 512) {
            int icl = idx % C2_ICC;
            int sp  = idx / C2_ICC;
            int r = sp / 18, cc = sp % 18;
            int gh = h0 + r - 1, gw = w0 + cc - 1;
            float v = 0.f;
            if ((unsigned)gh < 256u && (unsigned)gw < 256u)
                v = cin[((size_t)(b * HW + gh * 256 + gw)) * C1 + ic0 + icl];
            sIn[sp * C2_ICP + icl] = v;
        }
        for (int idx = tid; idx < C2_ICC * 1620; idx += 512) {
            int k   = idx % 9;
            int oc  = (idx / 9) % 180;
            int icl = idx / 1620;
            sW[icl * 1620 + oc * 9 + k] = w2[((size_t)(oc * C1 + ic0 + icl)) * 9 + k];
        }
        __syncthreads();
        for (int icl = 0; icl < C2_ICC; icl++) {
            float xv[9];
#pragma unroll
            for (int dr = 0; dr < 3; dr++)
#pragma unroll
                for (int dc = 0; dc < 3; dc++)
                    xv[dr * 3 + dc] = sIn[((pr + dr) * 18 + pc + dc) * C2_ICP + icl];
            const float* wp = sW + icl * 1620 + oc0 * 9;
#pragma unroll
            for (int j = 0; j < 90; j++) {
#pragma unroll
                for (int k = 0; k < 9; k++) acc[j] += xv[k] * wp[j * 9 + k];
            }
        }
    }
    size_t base = ((size_t)(b * HW + (h0 + pr) * 256 + (w0 + pc))) * CC + oc0;
    float2* o2 = (float2*)(out + base);   // base is 8B-aligned (oc0 in {0,90})
#pragma unroll
    for (int j = 0; j < 45; j++)
        o2[j] = make_float2(acc[2 * j] + b2[oc0 + 2 * j], acc[2 * j + 1] + b2[oc0 + 2 * j + 1]);
}

// ---------------- deterministic channel pooling (stage 1) ----------------
__global__ __launch_bounds__(192)
void pool_partial_kernel(const float* __restrict__ y, float* __restrict__ poolp) {
    __shared__ float s[32 * CC];
    int tid = threadIdx.x;
    int chunk = blockIdx.x;   // 0..31
    int b = blockIdx.y;
    size_t base = ((size_t)(b * HW) + (size_t)chunk * 2048) * CC;
    float acc = 0.f;
    for (int it = 0; it < 64; it++) {
        __syncthreads();
        size_t o = base + (size_t)it * 32 * CC;
        for (int idx = tid; idx < 32 * CC; idx += 192) s[idx] = y[o + idx];
        __syncthreads();
        if (tid < CC) {
#pragma unroll
            for (int t = 0; t < 32; t++) acc += s[t * CC + tid];
        }
    }
    if (tid < CC) poolp[(b * 32 + chunk) * CC + tid] = acc;
}

// ---------------- channel attention: mean -> relu(1x1) -> sigmoid(1x1) ----------------
__global__ void ca_kernel(const float* __restrict__ poolp,
                          const float* __restrict__ w1, const float* __restrict__ b1,
                          const float* __restrict__ w2, const float* __restrict__ b2,
                          float* __restrict__ ga) {
    int b = blockIdx.x;
    int t = threadIdx.x;
    __shared__ float mean[CC];
    __shared__ float sq[CA];
    if (t < CC) {
        float a = 0.f;
        for (int k = 0; k < 32; k++) a += poolp[(size_t)(b * 32 + k) * CC + t];
        mean[t] = a * (1.f / 65536.f);
    }
    __syncthreads();
    if (t < CA) {
        float a = b1[t];
        for (int c = 0; c < CC; c++) a += mean[c] * w1[t * CC + c];
        sq[t] = fmaxf(a, 0.f);
    }
    __syncthreads();
    if (t < CC) {
        float a = b2[t];
#pragma unroll
        for (int j = 0; j < CA; j++) a += sq[j] * w2[t * CA + j];
        ga[b * CC + t] = 0.01f / (1.f + expf(-a));   // sigmoid * CONV_SCALE
    }
}

// ---------------- window attention (one 8x8 window per block) ----------------
// smem: sX[64*180] | sQ/sK/sV[64*31] | sA[64*65] | sR[4096 ints]
__global__ __launch_bounds__(256)
void attn_kernel(const float* __restrict__ xn,
                 const float* __restrict__ qkv_w, const float* __restrict__ qkv_b,
                 const float* __restrict__ bias_table, const int* __restrict__ rpi,
                 float* __restrict__ attout) {
    extern __shared__ float sm[];
    float* sX = sm;                 // 11520
    float* sQ = sX + 11520;         // 64*31 = 1984
    float* sK = sQ + 1984;
    float* sV = sK + 1984;
    float* sA = sV + 1984;          // 64*65 = 4160
    int*   sR = (int*)(sA + 4160);  // 4096

    int tid = threadIdx.x;
    int wid = blockIdx.x;
    int b   = wid >> 10;
    int win = wid & 1023;
    int wr  = win >> 5, wc = win & 31;
    size_t xbase = (size_t)b * HW;

    for (int idx = tid; idx < 64 * CC; idx += 256) {
        int i = idx / CC, c = idx % CC;
        int gt = ((wr * 8 + (i >> 3)) << 8) + wc * 8 + (i & 7);
        sX[idx] = xn[(xbase + gt) * CC + c];
    }
    for (int idx = tid; idx < 4096; idx += 256) sR[idx] = rpi[idx];
    __syncthreads();

    const float scale = 0.18257418583505536f;  // 30^-0.5
    for (int h = 0; h < HEADS; h++) {
        // ---- QKV for this head (2 tokens per thread) ----
        for (int idx = tid; idx < 960; idx += 256) {
            int d  = idx % HD;
            int i0 = (idx / HD) * 2;
            int rq = h * HD + d;
            const float* wq = qkv_w + (size_t)rq * CC;
            const float* wk = wq + (size_t)CC * CC;
            const float* wv = wk + (size_t)CC * CC;
            float bq = qkv_b[rq], bk = qkv_b[CC + rq], bv = qkv_b[2 * CC + rq];
            float aq0 = bq, aq1 = bq, ak0 = bk, ak1 = bk, av0 = bv, av1 = bv;
            const float* x0 = sX + i0 * CC;
            const float* x1 = x0 + CC;
            for (int c = 0; c < CC; c++) {
                float wqv = wq[c], wkv = wk[c], wvv = wv[c];
                float xa = x0[c], xb = x1[c];
                aq0 += xa * wqv; aq1 += xb * wqv;
                ak0 += xa * wkv; ak1 += xb * wkv;
                av0 += xa * wvv; av1 += xb * wvv;
            }
            sQ[i0 * 31 + d] = aq0 * scale; sQ[(i0 + 1) * 31 + d] = aq1 * scale;
            sK[i0 * 31 + d] = ak0;         sK[(i0 + 1) * 31 + d] = ak1;
            sV[i0 * 31 + d] = av0;         sV[(i0 + 1) * 31 + d] = av1;
        }
        __syncthreads();
        // ---- scores + relative position bias ----
        for (int idx = tid; idx < 4096; idx += 256) {
            int i = idx >> 6, j = idx & 63;
            float s = bias_table[sR[idx] * HEADS + h];
            const float* qp = sQ + i * 31;
            const float* kp = sK + j * 31;
#pragma unroll
            for (int d = 0; d < HD; d++) s += qp[d] * kp[d];
            sA[i * 65 + j] = s;
        }
        __syncthreads();
        // ---- softmax (one thread per row) ----
        if (tid < 64) {
            float* row = sA + tid * 65;
            float m = row[0];
            for (int j = 1; j < 64; j++) m = fmaxf(m, row[j]);
            float sum = 0.f;
            for (int j = 0; j < 64; j++) { float e = expf(row[j] - m); row[j] = e; sum += e; }
            float inv = 1.f / sum;
            for (int j = 0; j < 64; j++) row[j] *= inv;
        }
        __syncthreads();
        // ---- attn @ V, write pre-proj out ----
        for (int idx = tid; idx < 960; idx += 256) {
            int d  = idx % HD;
            int i0 = (idx / HD) * 2, i1 = i0 + 1;
            const float* a0 = sA + i0 * 65;
            const float* a1 = a0 + 65;
            float o0 = 0.f, o1 = 0.f;
            for (int j = 0; j < 64; j++) {
                float vv = sV[j * 31 + d];
                o0 += a0[j] * vv; o1 += a1[j] * vv;
            }
            int gt0 = ((wr * 8 + (i0 >> 3)) << 8) + wc * 8 + (i0 & 7);
            int gt1 = ((wr * 8 + (i1 >> 3)) << 8) + wc * 8 + (i1 & 7);
            attout[(xbase + gt0) * CC + h * HD + d] = o0;
            attout[(xbase + gt1) * CC + h * HD + d] = o1;
        }
        __syncthreads();
    }
}

// ---------------- proj + residual + conv-branch add ----------------
// xmid = x + att @ proj_w.T + proj_b + y * ga   (ga already includes *0.01)
__global__ __launch_bounds__(192)
void proj_kernel(const float* __restrict__ x, const float* __restrict__ att,
                 const float* __restrict__ pw, const float* __restrict__ pb,
                 const float* __restrict__ y, const float* __restrict__ ga,
                 float* __restrict__ xmid) {
    extern __shared__ float sA[];  // [32][180]
    int tid = threadIdx.x;
    size_t tok0 = (size_t)blockIdx.x * 32;
    int b = (int)(tok0 >> 16);
    for (int idx = tid; idx < 32 * CC; idx += 192) sA[idx] = att[tok0 * CC + idx];
    __syncthreads();
    if (tid < CC) {
        int c = tid;
        float acc[32];
#pragma unroll
        for (int t = 0; t < 32; t++) acc[t] = 0.f;
        const float* wrow = pw + (size_t)c * CC;
        for (int k = 0; k < CC; k++) {
            float wv = wrow[k];
#pragma unroll
            for (int t = 0; t < 32; t++) acc[t] += sA[t * CC + k] * wv;
        }
        float bias = pb[c];
        float av   = ga[b * CC + c];
        for (int t = 0; t < 32; t++) {
            size_t o = (tok0 + t) * CC + c;
            xmid[o] = x[o] + acc[t] + bias + y[o] * av;
        }
    }
}

// ---------------- fc1 (180 -> 720) + GELU ----------------
__global__ __launch_bounds__(720)
void fc1_kernel(const float* __restrict__ xin, const float* __restrict__ w,
                const float* __restrict__ bb, float* __restrict__ hout) {
    extern __shared__ float sX[];  // [32][180]
    int tid = threadIdx.x;
    size_t tok0 = (size_t)blockIdx.x * 32;
    for (int idx = tid; idx < 32 * CC; idx += 720) sX[idx] = xin[tok0 * CC + idx];
    __syncthreads();
    int f = tid;  // < 720
    float acc[32];
#pragma unroll
    for (int t = 0; t < 32; t++) acc[t] = 0.f;
    const float* wrow = w + (size_t)f * CC;
    for (int k = 0; k < CC; k++) {
        float wv = wrow[k];
#pragma unroll
        for (int t = 0; t < 32; t++) acc[t] += sX[t * CC + k] * wv;
    }
    float bias = bb[f];
    for (int t = 0; t < 32; t++)
        hout[(tok0 + t) * FF + f] = gelu_f(acc[t] + bias);
}

// ---------------- fc2 (720 -> 180) + final residual ----------------
__global__ __launch_bounds__(192)
void fc2_kernel(const float* __restrict__ hbuf, const float* __restrict__ w,
                const float* __restrict__ bb, const float* __restrict__ xmid,
                float* __restrict__ out) {
    extern __shared__ float sH[];  // [32][720]
    int tid = threadIdx.x;
    size_t tok0 = (size_t)blockIdx.x * 32;
    for (int idx = tid; idx < 32 * FF; idx += 192) sH[idx] = hbuf[tok0 * FF + idx];
    __syncthreads();
    if (tid < CC) {
        int c = tid;
        float acc[32];
#pragma unroll
        for (int t = 0; t < 32; t++) acc[t] = 0.f;
        const float* wrow = w + (size_t)c * FF;
        for (int k = 0; k < FF; k++) {
            float wv = wrow[k];
#pragma unroll
            for (int t = 0; t < 32; t++) acc[t] += sH[t * FF + k] * wv;
        }
        float bias = bb[c];
        for (int t = 0; t < 32; t++) {
            size_t o = (tok0 + t) * CC + c;
            out[o] = xmid[o] + acc[t] + bias;
        }
    }
}

// ---------------- host launch ----------------
extern "C" void kernel_launch(void* const* d_in, const int* in_sizes, int n_in,
                              void* d_out, int out_size) {
    const float* x          = (const float*)d_in[0];
    const float* ln1_g      = (const float*)d_in[1];
    const float* ln1_b      = (const float*)d_in[2];
    const float* qkv_w      = (const float*)d_in[3];
    const float* qkv_b      = (const float*)d_in[4];
    const float* bias_table = (const float*)d_in[5];
    const float* proj_w     = (const float*)d_in[6];
    const float* proj_b     = (const float*)d_in[7];
    const float* cab_w1     = (const float*)d_in[8];
    const float* cab_b1     = (const float*)d_in[9];
    const float* cab_w2     = (const float*)d_in[10];
    const float* cab_b2     = (const float*)d_in[11];
    const float* ca_w1      = (const float*)d_in[12];
    const float* ca_b1      = (const float*)d_in[13];
    const float* ca_w2      = (const float*)d_in[14];
    const float* ca_b2      = (const float*)d_in[15];
    const float* ln2_g      = (const float*)d_in[16];
    const float* ln2_b      = (const float*)d_in[17];
    const float* fc1_w      = (const float*)d_in[18];
    const float* fc1_b      = (const float*)d_in[19];
    const float* fc2_w      = (const float*)d_in[20];
    const float* fc2_b      = (const float*)d_in[21];
    const int*   rpi        = (const int*)d_in[22];
    float* out = (float*)d_out;

    float *p_xn, *p_c1, *p_y, *p_att, *p_xmid, *p_h, *p_poolp, *p_a;
    cudaGetSymbolAddress((void**)&p_xn,    g_xn);
    cudaGetSymbolAddress((void**)&p_c1,    g_c1);
    cudaGetSymbolAddress((void**)&p_y,     g_y);
    cudaGetSymbolAddress((void**)&p_att,   g_att);
    cudaGetSymbolAddress((void**)&p_xmid,  g_xmid);
    cudaGetSymbolAddress((void**)&p_h,     g_h);
    cudaGetSymbolAddress((void**)&p_poolp, g_poolp);
    cudaGetSymbolAddress((void**)&p_a,     g_a);

    const int smem_conv1 = (324 * C1_ICP + C1_ICC * 540) * 4;   // 70416
    const int smem_conv2 = (324 * C2_ICP + C2_ICC * 1620) * 4;  // 79056
    const int smem_attn  = (11520 + 3 * 1984 + 4160 + 4096) * 4; // 102656
    const int smem_proj  = 32 * CC * 4;                          // 23040
    const int smem_fc1   = 32 * CC * 4;                          // 23040
    const int smem_fc2   = 32 * FF * 4;                          // 92160

    cudaFuncSetAttribute(conv1_kernel, cudaFuncAttributeMaxDynamicSharedMemorySize, smem_conv1);
    cudaFuncSetAttribute(conv2_kernel, cudaFuncAttributeMaxDynamicSharedMemorySize, smem_conv2);
    cudaFuncSetAttribute(attn_kernel,  cudaFuncAttributeMaxDynamicSharedMemorySize, smem_attn);
    cudaFuncSetAttribute(fc2_kernel,   cudaFuncAttributeMaxDynamicSharedMemorySize, smem_fc2);

    // 1. LN1
    ln_kernel<<<NTOK / 8, 256>>>(x, ln1_g, ln1_b, p_xn, NTOK);
    // 2. conv branch
    conv1_kernel<<<dim3(16, 16, BATCH), 256, smem_conv1>>>(p_xn, cab_w1, cab_b1, p_c1);
    conv2_kernel<<<dim3(16, 16, BATCH), 512, smem_conv2>>>(p_c1, cab_w2, cab_b2, p_y);
    pool_partial_kernel<<<dim3(32, BATCH), 192>>>(p_y, p_poolp);
    ca_kernel<<<BATCH, 192>>>(p_poolp, ca_w1, ca_b1, ca_w2, ca_b2, p_a);
    // 3. window attention
    attn_kernel<<<NWIN, 256, smem_attn>>>(p_xn, qkv_w, qkv_b, bias_table, rpi, p_att);
    // 4. proj + residual + conv add
    proj_kernel<<<NTOK / 32, 192, smem_proj>>>(x, p_att, proj_w, proj_b, p_y, p_a, p_xmid);
    // 5. MLP
    ln_kernel<<<NTOK / 8, 256>>>(p_xmid, ln2_g, ln2_b, p_xn, NTOK);
    fc1_kernel<<<NTOK / 32, 720, smem_fc1>>>(p_xn, fc1_w, fc1_b, p_h);
    fc2_kernel<<<NTOK / 32, 192, smem_fc2>>>(p_h, fc2_w, fc2_b, p_xmid, out);
}

// round 2
// speedup vs baseline: 4.8281x; 4.8281x over previous
#include <cuda_runtime.h>
#include <cuda_bf16.h>
#include <math.h>

// ---------------- Problem constants ----------------
#define BATCH   4
#define HW      65536           // 256*256
#define CC      180
#define C1D     60              // dim/3
#define CAD     6               // dim/30
#define FF      720             // 4*dim
#define HEADS   6
#define HD      30
#define NTOK    262144          // BATCH*HW
#define NWIN    4096

// ---------------- Scratch ----------------
__device__ float g_xn  [NTOK * CC];    // LN1 out, later LN2 out
__device__ float g_qkv [(size_t)NTOK * 540];
__device__ float g_c1  [NTOK * C1D];
__device__ float g_y   [NTOK * CC];
__device__ float g_att [NTOK * CC];
__device__ float g_xmid[NTOK * CC];
__device__ float g_h   [(size_t)NTOK * FF];
__device__ float g_poolp[BATCH * 32 * CC];
__device__ float g_a   [BATCH * CC];

__device__ __forceinline__ float gelu_f(float x) {
    return 0.5f * x * (1.0f + erff(x * 0.70710678118654752f));
}

// ---------------- LayerNorm (one warp per token) ----------------
__global__ void ln_kernel(const float* __restrict__ in, const float* __restrict__ g,
                          const float* __restrict__ bt, float* __restrict__ out, int ntok) {
    int gwarp = (blockIdx.x * blockDim.x + threadIdx.x) >> 5;
    int lane  = threadIdx.x & 31;
    if (gwarp >= ntok) return;
    const float* p = in + (size_t)gwarp * CC;
    float v[6];
    float s = 0.f, s2 = 0.f;
#pragma unroll
    for (int k = 0; k < 6; k++) {
        int c = lane + 32 * k;
        float xv = (c < CC) ? p[c] : 0.f;
        v[k] = xv; s += xv; s2 += xv * xv;
    }
#pragma unroll
    for (int o = 16; o > 0; o >>= 1) {
        s  += __shfl_xor_sync(0xffffffffu, s,  o);
        s2 += __shfl_xor_sync(0xffffffffu, s2, o);
    }
    float mean = s * (1.f / CC);
    float var  = s2 * (1.f / CC) - mean * mean;
    float inv  = rsqrtf(var + 1e-5f);
    float* q = out + (size_t)gwarp * CC;
#pragma unroll
    for (int k = 0; k < 6; k++) {
        int c = lane + 32 * k;
        if (c < CC) q[c] = (v[k] - mean) * inv * g[c] + bt[c];
    }
}

// ---------------- Register-tiled GEMM: out[M,N] = A[M,K] @ B[N,K]^T + bias ----------------
// BM=128, BN=64, BK=16; 256 threads; 8x4 micro-tile per thread.
// MODE 0: +bias  | 1: gelu(+bias) | 2: proj epilogue | 3: residual epilogue
template<int MODE>
__global__ __launch_bounds__(256)
void gemm_kernel(const float* __restrict__ A, const float* __restrict__ B,
                 const float* __restrict__ bias, const float* __restrict__ aux1,
                 const float* __restrict__ aux2, const float* __restrict__ ga,
                 float* __restrict__ out, int N, int K)
{
    __shared__ float As[16 * 132];
    __shared__ float Bs[16 * 68];
    const int tid = threadIdx.x;
    const int tx = tid & 15, ty = tid >> 4;
    const size_t m0 = (size_t)blockIdx.y * 128;
    const int n0 = blockIdx.x * 64;

    float c[8][4];
#pragma unroll
    for (int i = 0; i < 8; i++)
#pragma unroll
        for (int j = 0; j < 4; j++) c[i][j] = 0.f;

    for (int k0 = 0; k0 < K; k0 += 16) {
#pragma unroll
        for (int l = 0; l < 8; l++) {
            int idx = tid + l * 256;
            int m = idx >> 4, k = idx & 15;
            As[k * 132 + m] = (k0 + k < K) ? A[(m0 + m) * K + k0 + k] : 0.f;
        }
#pragma unroll
        for (int l = 0; l < 4; l++) {
            int idx = tid + l * 256;
            int n = idx >> 4, k = idx & 15;
            Bs[k * 68 + n] = (k0 + k < K && n0 + n < N)
                             ? B[(size_t)(n0 + n) * K + k0 + k] : 0.f;
        }
        __syncthreads();
#pragma unroll
        for (int kk = 0; kk < 16; kk++) {
            float4 A0 = *(const float4*)&As[kk * 132 + ty * 8];
            float4 A1 = *(const float4*)&As[kk * 132 + ty * 8 + 4];
            float4 B0 = *(const float4*)&Bs[kk * 68 + tx * 4];
            float a_[8] = {A0.x, A0.y, A0.z, A0.w, A1.x, A1.y, A1.z, A1.w};
            float b_[4] = {B0.x, B0.y, B0.z, B0.w};
#pragma unroll
            for (int i = 0; i < 8; i++)
#pragma unroll
                for (int j = 0; j < 4; j++) c[i][j] += a_[i] * b_[j];
        }
        __syncthreads();
    }

#pragma unroll
    for (int i = 0; i < 8; i++) {
        size_t row = m0 + ty * 8 + i;
        int bb = (int)(row >> 16);
#pragma unroll
        for (int j = 0; j < 4; j++) {
            int n = n0 + tx * 4 + j;
            if (n < N) {
                float v = c[i][j] + bias[n];
                size_t o = row * (size_t)N + n;
                if (MODE == 0)      out[o] = v;
                else if (MODE == 1) out[o] = gelu_f(v);
                else if (MODE == 2) out[o] = aux1[o] + v + aux2[o] * ga[bb * CC + n];
                else                out[o] = aux1[o] + v;
            }
        }
    }
}

// ---------------- conv1: NHWC 3x3, 180 -> 60, bias + GELU ----------------
// 16x16 px tile, 256 threads: thread = (4-px strip) x (15 oc group). acc[15][4].
#define IC1C 20
__global__ __launch_bounds__(256)
void conv1_kernel(const float* __restrict__ xn, const float* __restrict__ w1,
                  const float* __restrict__ b1, float* __restrict__ out) {
    extern __shared__ float sm[];
    float* sIn = sm;                  // [18*18][21]
    float* sW  = sm + 324 * 21;       // [20][540]
    const int tid = threadIdx.x;
    const int b  = blockIdx.z;
    const int h0 = blockIdx.y * 16, w0 = blockIdx.x * 16;
    const int og = tid & 3;           // 15 oc each
    const int strip = tid >> 2;       // 0..63
    const int r  = strip >> 2;        // 0..15
    const int c0 = (strip & 3) * 4;   // 0,4,8,12

    float acc[15][4];
#pragma unroll
    for (int o = 0; o < 15; o++)
#pragma unroll
        for (int p = 0; p < 4; p++) acc[o][p] = 0.f;

    for (int ic0 = 0; ic0 < CC; ic0 += IC1C) {
        __syncthreads();
        for (int idx = tid; idx < 324 * IC1C; idx += 256) {
            int icl = idx % IC1C;
            int sp  = idx / IC1C;
            int rr = sp / 18, cc = sp % 18;
            int gh = h0 + rr - 1, gw = w0 + cc - 1;
            float v = 0.f;
            if ((unsigned)gh < 256u && (unsigned)gw < 256u)
                v = xn[((size_t)(b * HW + gh * 256 + gw)) * CC + ic0 + icl];
            sIn[sp * 21 + icl] = v;
        }
        for (int idx = tid; idx < IC1C * 540; idx += 256) {
            int k   = idx % 9;
            int oc  = (idx / 9) % 60;
            int icl = idx / 540;
            sW[icl * 540 + oc * 9 + k] = w1[((size_t)(oc * CC + ic0 + icl)) * 9 + k];
        }
        __syncthreads();
        for (int icl = 0; icl < IC1C; icl++) {
            float xr[3][6];
#pragma unroll
            for (int dr = 0; dr < 3; dr++)
#pragma unroll
                for (int cc = 0; cc < 6; cc++)
                    xr[dr][cc] = sIn[((r + dr) * 18 + c0 + cc) * 21 + icl];
#pragma unroll
            for (int o = 0; o < 15; o++) {
                const float* wp = &sW[icl * 540 + (og * 15 + o) * 9];
                float wv[9];
#pragma unroll
                for (int k = 0; k < 9; k++) wv[k] = wp[k];
#pragma unroll
                for (int dr = 0; dr < 3; dr++)
#pragma unroll
                    for (int dc = 0; dc < 3; dc++)
#pragma unroll
                        for (int p = 0; p < 4; p++)
                            acc[o][p] += xr[dr][p + dc] * wv[dr * 3 + dc];
            }
        }
    }
    __syncthreads();
    float* sOut = sm;   // [256][61] = 15616 floats (fits in 17604-float region)
#pragma unroll
    for (int o = 0; o < 15; o++) {
        int oc = og * 15 + o;
        float bv = b1[oc];
#pragma unroll
        for (int p = 0; p < 4; p++)
            sOut[(r * 16 + c0 + p) * 61 + oc] = gelu_f(acc[o][p] + bv);
    }
    __syncthreads();
    for (int idx = tid; idx < 256 * 60; idx += 256) {
        int px = idx / 60, oc = idx % 60;
        int gh = h0 + (px >> 4), gw = w0 + (px & 15);
        out[((size_t)(b * HW + gh * 256 + gw)) * C1D + oc] = sOut[px * 61 + oc];
    }
}

// ---------------- conv2: NHWC 3x3, 60 -> 180, bias ----------------
// same tiling; blockIdx.z = b*3 + ocg (60-oc groups)
#define IC2C 20
__global__ __launch_bounds__(256)
void conv2_kernel(const float* __restrict__ cin, const float* __restrict__ w2,
                  const float* __restrict__ b2, float* __restrict__ out) {
    extern __shared__ float sm[];
    float* sIn = sm;                  // [18*18][21]
    float* sW  = sm + 324 * 21;       // [20][540]
    const int tid = threadIdx.x;
    const int b   = blockIdx.z / 3;
    const int ocg = blockIdx.z % 3;
    const int h0 = blockIdx.y * 16, w0 = blockIdx.x * 16;
    const int og = tid & 3;
    const int strip = tid >> 2;
    const int r  = strip >> 2;
    const int c0 = (strip & 3) * 4;

    float acc[15][4];
#pragma unroll
    for (int o = 0; o < 15; o++)
#pragma unroll
        for (int p = 0; p < 4; p++) acc[o][p] = 0.f;

    for (int ic0 = 0; ic0 < C1D; ic0 += IC2C) {
        __syncthreads();
        for (int idx = tid; idx < 324 * IC2C; idx += 256) {
            int icl = idx % IC2C;
            int sp  = idx / IC2C;
            int rr = sp / 18, cc = sp % 18;
            int gh = h0 + rr - 1, gw = w0 + cc - 1;
            float v = 0.f;
            if ((unsigned)gh < 256u && (unsigned)gw < 256u)
                v = cin[((size_t)(b * HW + gh * 256 + gw)) * C1D + ic0 + icl];
            sIn[sp * 21 + icl] = v;
        }
        for (int idx = tid; idx < IC2C * 540; idx += 256) {
            int k   = idx % 9;
            int ocl = (idx / 9) % 60;
            int icl = idx / 540;
            sW[icl * 540 + ocl * 9 + k] =
                w2[((size_t)((ocg * 60 + ocl) * C1D + ic0 + icl)) * 9 + k];
        }
        __syncthreads();
        for (int icl = 0; icl < IC2C; icl++) {
            float xr[3][6];
#pragma unroll
            for (int dr = 0; dr < 3; dr++)
#pragma unroll
                for (int cc = 0; cc < 6; cc++)
                    xr[dr][cc] = sIn[((r + dr) * 18 + c0 + cc) * 21 + icl];
#pragma unroll
            for (int o = 0; o < 15; o++) {
                const float* wp = &sW[icl * 540 + (og * 15 + o) * 9];
                float wv[9];
#pragma unroll
                for (int k = 0; k < 9; k++) wv[k] = wp[k];
#pragma unroll
                for (int dr = 0; dr < 3; dr++)
#pragma unroll
                    for (int dc = 0; dc < 3; dc++)
#pragma unroll
                        for (int p = 0; p < 4; p++)
                            acc[o][p] += xr[dr][p + dc] * wv[dr * 3 + dc];
            }
        }
    }
    __syncthreads();
    float* sOut = sm;   // [256][61]
#pragma unroll
    for (int o = 0; o < 15; o++) {
        int ocl = og * 15 + o;
        float bv = b2[ocg * 60 + ocl];
#pragma unroll
        for (int p = 0; p < 4; p++)
            sOut[(r * 16 + c0 + p) * 61 + ocl] = acc[o][p] + bv;
    }
    __syncthreads();
    for (int idx = tid; idx < 256 * 60; idx += 256) {
        int px = idx / 60, oc = idx % 60;
        int gh = h0 + (px >> 4), gw = w0 + (px & 15);
        out[((size_t)(b * HW + gh * 256 + gw)) * CC + ocg * 60 + oc] = sOut[px * 61 + oc];
    }
}

// ---------------- deterministic channel pooling (stage 1) ----------------
__global__ __launch_bounds__(192)
void pool_partial_kernel(const float* __restrict__ y, float* __restrict__ poolp) {
    __shared__ float s[32 * CC];
    int tid = threadIdx.x;
    int chunk = blockIdx.x;
    int b = blockIdx.y;
    size_t base = ((size_t)(b * HW) + (size_t)chunk * 2048) * CC;
    float acc = 0.f;
    for (int it = 0; it < 64; it++) {
        __syncthreads();
        size_t o = base + (size_t)it * 32 * CC;
        for (int idx = tid; idx < 32 * CC; idx += 192) s[idx] = y[o + idx];
        __syncthreads();
        if (tid < CC) {
#pragma unroll
            for (int t = 0; t < 32; t++) acc += s[t * CC + tid];
        }
    }
    if (tid < CC) poolp[(b * 32 + chunk) * CC + tid] = acc;
}

// ---------------- channel attention ----------------
__global__ void ca_kernel(const float* __restrict__ poolp,
                          const float* __restrict__ w1, const float* __restrict__ b1,
                          const float* __restrict__ w2, const float* __restrict__ b2,
                          float* __restrict__ ga) {
    int b = blockIdx.x;
    int t = threadIdx.x;
    __shared__ float mean[CC];
    __shared__ float sq[CAD];
    if (t < CC) {
        float a = 0.f;
        for (int k = 0; k < 32; k++) a += poolp[(size_t)(b * 32 + k) * CC + t];
        mean[t] = a * (1.f / 65536.f);
    }
    __syncthreads();
    if (t < CAD) {
        float a = b1[t];
        for (int c = 0; c < CC; c++) a += mean[c] * w1[t * CC + c];
        sq[t] = fmaxf(a, 0.f);
    }
    __syncthreads();
    if (t < CC) {
        float a = b2[t];
#pragma unroll
        for (int j = 0; j < CAD; j++) a += sq[j] * w2[t * CAD + j];
        ga[b * CC + t] = 0.01f / (1.f + expf(-a));
    }
}

// ---------------- window attention (QKV precomputed globally) ----------------
__global__ __launch_bounds__(256)
void attn_kernel(const float* __restrict__ qkv, const float* __restrict__ bias_table,
                 const int* __restrict__ rpi, float* __restrict__ attout) {
    extern __shared__ float sm[];
    float* sQ = sm;                  // 64*33
    float* sK = sQ + 64 * 33;
    float* sV = sK + 64 * 33;
    float* sA = sV + 64 * 33;        // 64*66
    int*   sR = (int*)(sA + 64 * 66);

    const int tid = threadIdx.x;
    const int b   = blockIdx.x >> 10;
    const int win = blockIdx.x & 1023;
    const int wr  = win >> 5, wc = win & 31;
    const int row0 = b * HW + (wr * 8) * 256 + wc * 8;

    for (int idx = tid; idx < 4096; idx += 256) sR[idx] = rpi[idx];

    const float scale = 0.18257418583505536f;  // 30^-0.5
    for (int h = 0; h < HEADS; h++) {
        __syncthreads();
        for (int idx = tid; idx < 1920; idx += 256) {
            int i = idx / 30, d = idx % 30;
            int gt = row0 + (i >> 3) * 256 + (i & 7);
            const float* p = qkv + (size_t)gt * 540 + h * HD + d;
            sQ[i * 33 + d] = p[0] * scale;
            sK[i * 33 + d] = p[180];
            sV[i * 33 + d] = p[360];
        }
        __syncthreads();
        // scores + bias (2 rows per thread-iter)
        for (int idx = tid; idx < 2048; idx += 256) {
            int j = idx & 63, ip = idx >> 6;
            int i0 = ip * 2, i1 = i0 + 1;
            float s0 = bias_table[sR[i0 * 64 + j] * HEADS + h];
            float s1 = bias_table[sR[i1 * 64 + j] * HEADS + h];
            const float* q0 = sQ + i0 * 33;
            const float* q1 = sQ + i1 * 33;
            const float* kp = sK + j * 33;
#pragma unroll
            for (int d = 0; d < HD; d++) {
                float kv = kp[d];
                s0 += q0[d] * kv; s1 += q1[d] * kv;
            }
            sA[i0 * 66 + j] = s0; sA[i1 * 66 + j] = s1;
        }
        __syncthreads();
        // softmax: warp per row
        {
            int w = tid >> 5, lane = tid & 31;
            for (int rrow = w; rrow < 64; rrow += 8) {
                float* row = sA + rrow * 66;
                float v0 = row[lane], v1 = row[lane + 32];
                float m = fmaxf(v0, v1);
#pragma unroll
                for (int o = 16; o > 0; o >>= 1) m = fmaxf(m, __shfl_xor_sync(0xffffffffu, m, o));
                float e0 = expf(v0 - m), e1 = expf(v1 - m);
                float s = e0 + e1;
#pragma unroll
                for (int o = 16; o > 0; o >>= 1) s += __shfl_xor_sync(0xffffffffu, s, o);
                float inv = 1.f / s;
                row[lane] = e0 * inv; row[lane + 32] = e1 * inv;
            }
        }
        __syncthreads();
        // AV (2 rows per thread-iter)
        for (int idx = tid; idx < 960; idx += 256) {
            int d = idx % 30, ip = idx / 30;
            int i0 = ip * 2, i1 = i0 + 1;
            const float* a0 = sA + i0 * 66;
            const float* a1 = sA + i1 * 66;
            float o0 = 0.f, o1 = 0.f;
#pragma unroll 8
            for (int j = 0; j < 64; j++) {
                float vv = sV[j * 33 + d];
                o0 += a0[j] * vv; o1 += a1[j] * vv;
            }
            int gt0 = row0 + (i0 >> 3) * 256 + (i0 & 7);
            int gt1 = row0 + (i1 >> 3) * 256 + (i1 & 7);
            attout[(size_t)gt0 * CC + h * HD + d] = o0;
            attout[(size_t)gt1 * CC + h * HD + d] = o1;
        }
    }
}

// ---------------- host launch ----------------
extern "C" void kernel_launch(void* const* d_in, const int* in_sizes, int n_in,
                              void* d_out, int out_size) {
    const float* x          = (const float*)d_in[0];
    const float* ln1_g      = (const float*)d_in[1];
    const float* ln1_b      = (const float*)d_in[2];
    const float* qkv_w      = (const float*)d_in[3];
    const float* qkv_b      = (const float*)d_in[4];
    const float* bias_table = (const float*)d_in[5];
    const float* proj_w     = (const float*)d_in[6];
    const float* proj_b     = (const float*)d_in[7];
    const float* cab_w1     = (const float*)d_in[8];
    const float* cab_b1     = (const float*)d_in[9];
    const float* cab_w2     = (const float*)d_in[10];
    const float* cab_b2     = (const float*)d_in[11];
    const float* ca_w1      = (const float*)d_in[12];
    const float* ca_b1      = (const float*)d_in[13];
    const float* ca_w2      = (const float*)d_in[14];
    const float* ca_b2      = (const float*)d_in[15];
    const float* ln2_g      = (const float*)d_in[16];
    const float* ln2_b      = (const float*)d_in[17];
    const float* fc1_w      = (const float*)d_in[18];
    const float* fc1_b      = (const float*)d_in[19];
    const float* fc2_w      = (const float*)d_in[20];
    const float* fc2_b      = (const float*)d_in[21];
    const int*   rpi        = (const int*)d_in[22];
    float* out = (float*)d_out;

    float *p_xn, *p_qkv, *p_c1, *p_y, *p_att, *p_xmid, *p_h, *p_poolp, *p_a;
    cudaGetSymbolAddress((void**)&p_xn,    g_xn);
    cudaGetSymbolAddress((void**)&p_qkv,   g_qkv);
    cudaGetSymbolAddress((void**)&p_c1,    g_c1);
    cudaGetSymbolAddress((void**)&p_y,     g_y);
    cudaGetSymbolAddress((void**)&p_att,   g_att);
    cudaGetSymbolAddress((void**)&p_xmid,  g_xmid);
    cudaGetSymbolAddress((void**)&p_h,     g_h);
    cudaGetSymbolAddress((void**)&p_poolp, g_poolp);
    cudaGetSymbolAddress((void**)&p_a,     g_a);

    const int smem_conv = (324 * 21 + 20 * 540) * 4;                 // 70416
    const int smem_attn = (3 * 64 * 33 + 64 * 66) * 4 + 4096 * 4;    // 58624

    cudaFuncSetAttribute(conv1_kernel, cudaFuncAttributeMaxDynamicSharedMemorySize, smem_conv);
    cudaFuncSetAttribute(conv2_kernel, cudaFuncAttributeMaxDynamicSharedMemorySize, smem_conv);
    cudaFuncSetAttribute(attn_kernel,  cudaFuncAttributeMaxDynamicSharedMemorySize, smem_attn);

    // 1. LN1
    ln_kernel<<<NTOK / 8, 256>>>(x, ln1_g, ln1_b, p_xn, NTOK);
    // 2. conv branch
    conv1_kernel<<<dim3(16, 16, BATCH), 256, smem_conv>>>(p_xn, cab_w1, cab_b1, p_c1);
    conv2_kernel<<<dim3(16, 16, BATCH * 3), 256, smem_conv>>>(p_c1, cab_w2, cab_b2, p_y);
    pool_partial_kernel<<<dim3(32, BATCH), 192>>>(p_y, p_poolp);
    ca_kernel<<<BATCH, 192>>>(p_poolp, ca_w1, ca_b1, ca_w2, ca_b2, p_a);
    // 3. global QKV GEMM then window attention
    gemm_kernel<0><<<dim3(9, 2048), 256>>>(p_xn, qkv_w, qkv_b, p_xn, p_xn, p_a,
                                           p_qkv, 540, CC);
    attn_kernel<<<NWIN, 256, smem_attn>>>(p_qkv, bias_table, rpi, p_att);
    // 4. proj + residual + conv add
    gemm_kernel<2><<<dim3(3, 2048), 256>>>(p_att, proj_w, proj_b, x, p_y, p_a,
                                           p_xmid, CC, CC);
    // 5. MLP
    ln_kernel<<<NTOK / 8, 256>>>(p_xmid, ln2_g, ln2_b, p_xn, NTOK);
    gemm_kernel<1><<<dim3(12, 2048), 256>>>(p_xn, fc1_w, fc1_b, p_xn, p_xn, p_a,
                                            p_h, FF, CC);
    gemm_kernel<3><<<dim3(3, 2048), 256>>>(p_h, fc2_w, fc2_b, p_xmid, p_xmid, p_a,
                                           out, CC, FF);
}

// round 5
// speedup vs baseline: 6.8320x; 1.4151x over previous
#include <cuda_runtime.h>
#include <cuda_bf16.h>
#include <math.h>
#include <stdint.h>

// ---------------- Problem constants ----------------
#define BATCH   4
#define HW      65536
#define CC      180
#define C1D     60
#define CAD     6
#define FF      720
#define HEADS   6
#define HD      30
#define NTOK    262144
#define NWIN    4096

// ---------------- Scratch ----------------
__device__ float g_xn  [NTOK * CC];
__device__ float g_qkv [(size_t)NTOK * 540];
__device__ float g_c1  [NTOK * C1D];
__device__ float g_y   [NTOK * CC];
__device__ float g_xmid[NTOK * CC];
__device__ float g_poolp[1024 * CC];
__device__ float g_a   [BATCH * CC];

__device__ __nv_bfloat16 g_xnh[NTOK * CC],  g_xnl[NTOK * CC];
__device__ __nv_bfloat16 g_atth[NTOK * CC], g_attl[NTOK * CC];
__device__ __nv_bfloat16 g_hh[(size_t)NTOK * FF], g_hl[(size_t)NTOK * FF];
__device__ __nv_bfloat16 g_wqh[540*CC],  g_wql[540*CC];
__device__ __nv_bfloat16 g_wph[CC*CC],   g_wpl[CC*CC];
__device__ __nv_bfloat16 g_wf1h[FF*CC],  g_wf1l[FF*CC];
__device__ __nv_bfloat16 g_wf2h[CC*FF],  g_wf2l[CC*FF];

__device__ __forceinline__ float gelu_f(float x) {
    return 0.5f * x * (1.0f + erff(x * 0.70710678118654752f));
}
__device__ __forceinline__ void split2(float f, __nv_bfloat16& h, __nv_bfloat16& l) {
    h = __float2bfloat16(f);
    l = __float2bfloat16(f - __bfloat162float(h));
}
__device__ __forceinline__ uint32_t smem_u32(const void* p) {
    uint32_t a;
    asm("{ .reg .u64 t; cvta.to.shared.u64 t, %1; cvt.u32.u64 %0, t; }" : "=r"(a) : "l"(p));
    return a;
}
__device__ __forceinline__ void ldsm_x4(uint32_t* r, uint32_t addr) {
    asm volatile("ldmatrix.sync.aligned.m8n8.x4.shared.b16 {%0,%1,%2,%3}, [%4];"
        : "=r"(r[0]), "=r"(r[1]), "=r"(r[2]), "=r"(r[3]) : "r"(addr));
}
__device__ __forceinline__ void mma16816(float* c, const uint32_t* a, const uint32_t* b) {
    asm volatile("mma.sync.aligned.m16n8k16.row.col.f32.bf16.bf16.f32 "
        "{%0,%1,%2,%3}, {%4,%5,%6,%7}, {%8,%9}, {%0,%1,%2,%3};"
        : "+f"(c[0]), "+f"(c[1]), "+f"(c[2]), "+f"(c[3])
        : "r"(a[0]), "r"(a[1]), "r"(a[2]), "r"(a[3]), "r"(b[0]), "r"(b[1]));
}

// ---------------- weight split prep ----------------
__global__ void split_kernel(const float* __restrict__ src, __nv_bfloat16* __restrict__ hi,
                             __nv_bfloat16* __restrict__ lo, int n) {
    int i = blockIdx.x * 256 + threadIdx.x;
    if (i < n) { __nv_bfloat16 h, l; split2(src[i], h, l); hi[i] = h; lo[i] = l; }
}

// ---------------- LayerNorm: fp32 out + bf16 hi/lo ----------------
__global__ void ln_kernel(const float* __restrict__ in, const float* __restrict__ g,
                          const float* __restrict__ bt, float* __restrict__ out,
                          __nv_bfloat16* __restrict__ oh, __nv_bfloat16* __restrict__ ol,
                          int ntok) {
    int gwarp = (blockIdx.x * blockDim.x + threadIdx.x) >> 5;
    int lane  = threadIdx.x & 31;
    if (gwarp >= ntok) return;
    const float* p = in + (size_t)gwarp * CC;
    float v[6]; float s = 0.f, s2 = 0.f;
#pragma unroll
    for (int k = 0; k < 6; k++) {
        int c = lane + 32 * k;
        float xv = (c < CC) ? p[c] : 0.f;
        v[k] = xv; s += xv; s2 += xv * xv;
    }
#pragma unroll
    for (int o = 16; o > 0; o >>= 1) {
        s  += __shfl_xor_sync(0xffffffffu, s,  o);
        s2 += __shfl_xor_sync(0xffffffffu, s2, o);
    }
    float mean = s * (1.f / CC);
    float var  = s2 * (1.f / CC) - mean * mean;
    float inv  = rsqrtf(var + 1e-5f);
    size_t base = (size_t)gwarp * CC;
#pragma unroll
    for (int k = 0; k < 6; k++) {
        int c = lane + 32 * k;
        if (c < CC) {
            float y = (v[k] - mean) * inv * g[c] + bt[c];
            out[base + c] = y;
            __nv_bfloat16 h, l; split2(y, h, l);
            oh[base + c] = h; ol[base + c] = l;
        }
    }
}

// ---------------- bf16 mma.sync GEMM with hi/lo split ----------------
// out[M,N] = (Ah+Al)[M,K] @ (Bh+Bl)[N,K]^T  (3 passes, fp32 accum)
// MODE 0: fp32 +bias | 1: gelu(+bias)->bf16 hi/lo | 2: proj epi | 3: fc2 epi
#define LDT 72
#define SM_AH 0
#define SM_AL (128 * LDT)
#define SM_BH (2 * 128 * LDT)
#define SM_BL (2 * 128 * LDT + 64 * LDT)
#define SMEM_MMA ((2 * 128 * LDT + 2 * 64 * LDT) * 2)   // bytes = 55296

template<int MODE>
__global__ __launch_bounds__(256)
void mma_gemm(const __nv_bfloat16* __restrict__ Ah, const __nv_bfloat16* __restrict__ Al,
              const __nv_bfloat16* __restrict__ Bh, const __nv_bfloat16* __restrict__ Bl,
              const float* __restrict__ bias,
              const float* __restrict__ aux1, const float* __restrict__ aux2,
              const float* __restrict__ ga,
              float* __restrict__ outf, __nv_bfloat16* __restrict__ outh,
              __nv_bfloat16* __restrict__ outl, int N, int K)
{
    extern __shared__ __nv_bfloat16 sm[];
    __nv_bfloat16* sAh = sm + SM_AH;
    __nv_bfloat16* sAl = sm + SM_AL;
    __nv_bfloat16* sBh = sm + SM_BH;
    __nv_bfloat16* sBl = sm + SM_BL;

    const int tid  = threadIdx.x;
    const int warp = tid >> 5, lane = tid & 31;
    const int wm = warp >> 1, wn = warp & 1;           // 4 x 2 warp grid
    const size_t m0 = (size_t)blockIdx.y * 128;
    const int n0 = blockIdx.x * 64;

    float acc[2][4][4];
#pragma unroll
    for (int i = 0; i < 2; i++)
#pragma unroll
        for (int j = 0; j < 4; j++)
#pragma unroll
            for (int c = 0; c < 4; c++) acc[i][j][c] = 0.f;

    // ldmatrix source addresses (element offsets within tiles)
    const int aRow = (lane & 15), aColOff = (lane >> 4) << 3;
    const int bRow = ((lane >> 4) << 3) + (lane & 7), bColOff = ((lane >> 3) & 1) << 3;

    const int nch = (K + 63) / 64;
    for (int kc = 0; kc < nch; kc++) {
        const int kbase = kc * 64;
        // ---- stage A hi/lo: 128 rows x 32 bf16-pairs each ----
        for (int i = tid; i < 128 * 32; i += 256) {
            int row = i >> 5, kp = i & 31;
            int k = kbase + kp * 2;
            uint32_t vh = 0, vl = 0;
            if (k < K) {
                size_t off = (m0 + row) * (size_t)K + k;
                vh = *(const uint32_t*)(Ah + off);
                vl = *(const uint32_t*)(Al + off);
            }
            *(uint32_t*)(sAh + row * LDT + kp * 2) = vh;
            *(uint32_t*)(sAl + row * LDT + kp * 2) = vl;
        }
        // ---- stage B hi/lo: 64 rows x 32 pairs ----
        for (int i = tid; i < 64 * 32; i += 256) {
            int row = i >> 5, kp = i & 31;
            int k = kbase + kp * 2;
            uint32_t vh = 0, vl = 0;
            if (k < K && n0 + row < N) {
                size_t off = (size_t)(n0 + row) * K + k;
                vh = *(const uint32_t*)(Bh + off);
                vl = *(const uint32_t*)(Bl + off);
            }
            *(uint32_t*)(sBh + row * LDT + kp * 2) = vh;
            *(uint32_t*)(sBl + row * LDT + kp * 2) = vl;
        }
        __syncthreads();

#pragma unroll
        for (int ks = 0; ks < 4; ks++) {
            const int kb = ks * 16;
            uint32_t aH[2][4], aL[2][4], bH[4][2], bL[4][2];
#pragma unroll
            for (int mi = 0; mi < 2; mi++) {
                int r = wm * 32 + mi * 16 + aRow;
                uint32_t adr = smem_u32(sAh + r * LDT + kb + aColOff);
                ldsm_x4(aH[mi], adr);
                ldsm_x4(aL[mi], adr + (SM_AL - SM_AH) * 2);
            }
#pragma unroll
            for (int nf = 0; nf < 2; nf++) {
                int r = wn * 32 + nf * 16 + bRow;
                uint32_t adr = smem_u32(sBh + r * LDT + kb + bColOff);
                uint32_t t[4];
                ldsm_x4(t, adr);
                bH[nf*2][0] = t[0]; bH[nf*2][1] = t[1];
                bH[nf*2+1][0] = t[2]; bH[nf*2+1][1] = t[3];
                ldsm_x4(t, adr + (SM_BL - SM_BH) * 2);
                bL[nf*2][0] = t[0]; bL[nf*2][1] = t[1];
                bL[nf*2+1][0] = t[2]; bL[nf*2+1][1] = t[3];
            }
#pragma unroll
            for (int mi = 0; mi < 2; mi++)
#pragma unroll
                for (int ni = 0; ni < 4; ni++) {
                    mma16816(acc[mi][ni], aH[mi], bH[ni]);
                    mma16816(acc[mi][ni], aH[mi], bL[ni]);
                    mma16816(acc[mi][ni], aL[mi], bH[ni]);
                }
        }
        __syncthreads();
    }

    // ---- epilogue ----
#pragma unroll
    for (int mi = 0; mi < 2; mi++)
#pragma unroll
        for (int hh = 0; hh < 2; hh++) {
            size_t row = m0 + wm * 32 + mi * 16 + (lane >> 2) + hh * 8;
            int bb = (int)(row >> 16);
#pragma unroll
            for (int ni = 0; ni < 4; ni++) {
                int n_ = n0 + wn * 32 + ni * 8 + (lane & 3) * 2;
                if (n_ >= N) continue;
                float v0 = acc[mi][ni][hh * 2 + 0] + bias[n_];
                float v1 = acc[mi][ni][hh * 2 + 1] + bias[n_ + 1];
                size_t o = row * (size_t)N + n_;
                if (MODE == 0) {
                    *(float2*)(outf + o) = make_float2(v0, v1);
                } else if (MODE == 1) {
                    float gg0 = gelu_f(v0), gg1 = gelu_f(v1);
                    __nv_bfloat16 h0, l0, h1, l1;
                    split2(gg0, h0, l0); split2(gg1, h1, l1);
                    __nv_bfloat162 hp; hp.x = h0; hp.y = h1;
                    __nv_bfloat162 lp; lp.x = l0; lp.y = l1;
                    *(__nv_bfloat162*)(outh + o) = hp;
                    *(__nv_bfloat162*)(outl + o) = lp;
                } else if (MODE == 2) {
                    float2 xv = *(const float2*)(aux1 + o);
                    float2 yv = *(const float2*)(aux2 + o);
                    *(float2*)(outf + o) = make_float2(
                        xv.x + v0 + yv.x * ga[bb * CC + n_],
                        xv.y + v1 + yv.y * ga[bb * CC + n_ + 1]);
                } else {
                    float2 xm = *(const float2*)(aux1 + o);
                    *(float2*)(outf + o) = make_float2(xm.x + v0, xm.y + v1);
                }
            }
        }
}

// ---------------- conv1: NHWC 3x3, 180 -> 60, bias + GELU ----------------
#define IC1C 20
__global__ __launch_bounds__(256)
void conv1_kernel(const float* __restrict__ xn, const float* __restrict__ w1,
                  const float* __restrict__ b1, float* __restrict__ out) {
    extern __shared__ float smf[];
    float* sIn = smf;
    float* sW  = smf + 324 * 21;
    const int tid = threadIdx.x;
    const int b  = blockIdx.z;
    const int h0 = blockIdx.y * 16, w0 = blockIdx.x * 16;
    const int og = tid & 3;
    const int strip = tid >> 2;
    const int r  = strip >> 2;
    const int c0 = (strip & 3) * 4;

    float acc[15][4];
#pragma unroll
    for (int o = 0; o < 15; o++)
#pragma unroll
        for (int p = 0; p < 4; p++) acc[o][p] = 0.f;

    for (int ic0 = 0; ic0 < CC; ic0 += IC1C) {
        __syncthreads();
        for (int idx = tid; idx < 324 * IC1C; idx += 256) {
            int icl = idx % IC1C;
            int sp  = idx / IC1C;
            int rr = sp / 18, cc = sp % 18;
            int gh = h0 + rr - 1, gw = w0 + cc - 1;
            float v = 0.f;
            if ((unsigned)gh < 256u && (unsigned)gw < 256u)
                v = xn[((size_t)(b * HW + gh * 256 + gw)) * CC + ic0 + icl];
            sIn[sp * 21 + icl] = v;
        }
        for (int idx = tid; idx < IC1C * 540; idx += 256) {
            int k   = idx % 9;
            int oc  = (idx / 9) % 60;
            int icl = idx / 540;
            sW[icl * 540 + oc * 9 + k] = w1[((size_t)(oc * CC + ic0 + icl)) * 9 + k];
        }
        __syncthreads();
        for (int icl = 0; icl < IC1C; icl++) {
            float xr[3][6];
#pragma unroll
            for (int dr = 0; dr < 3; dr++)
#pragma unroll
                for (int cc = 0; cc < 6; cc++)
                    xr[dr][cc] = sIn[((r + dr) * 18 + c0 + cc) * 21 + icl];
#pragma unroll
            for (int o = 0; o < 15; o++) {
                const float* wp = &sW[icl * 540 + (og * 15 + o) * 9];
                float wv[9];
#pragma unroll
                for (int k = 0; k < 9; k++) wv[k] = wp[k];
#pragma unroll
                for (int dr = 0; dr < 3; dr++)
#pragma unroll
                    for (int dc = 0; dc < 3; dc++)
#pragma unroll
                        for (int p = 0; p < 4; p++)
                            acc[o][p] += xr[dr][p + dc] * wv[dr * 3 + dc];
            }
        }
    }
    __syncthreads();
    float* sOut = smf;
#pragma unroll
    for (int o = 0; o < 15; o++) {
        int oc = og * 15 + o;
        float bv = b1[oc];
#pragma unroll
        for (int p = 0; p < 4; p++)
            sOut[(r * 16 + c0 + p) * 61 + oc] = gelu_f(acc[o][p] + bv);
    }
    __syncthreads();
    for (int idx = tid; idx < 256 * 60; idx += 256) {
        int px = idx / 60, oc = idx % 60;
        int gh = h0 + (px >> 4), gw = w0 + (px & 15);
        out[((size_t)(b * HW + gh * 256 + gw)) * C1D + oc] = sOut[px * 61 + oc];
    }
}

// ---------------- conv2: NHWC 3x3, 60 -> 180, bias ----------------
#define IC2C 20
__global__ __launch_bounds__(256)
void conv2_kernel(const float* __restrict__ cin, const float* __restrict__ w2,
                  const float* __restrict__ b2, float* __restrict__ out) {
    extern __shared__ float smf[];
    float* sIn = smf;
    float* sW  = smf + 324 * 21;
    const int tid = threadIdx.x;
    const int b   = blockIdx.z / 3;
    const int ocg = blockIdx.z % 3;
    const int h0 = blockIdx.y * 16, w0 = blockIdx.x * 16;
    const int og = tid & 3;
    const int strip = tid >> 2;
    const int r  = strip >> 2;
    const int c0 = (strip & 3) * 4;

    float acc[15][4];
#pragma unroll
    for (int o = 0; o < 15; o++)
#pragma unroll
        for (int p = 0; p < 4; p++) acc[o][p] = 0.f;

    for (int ic0 = 0; ic0 < C1D; ic0 += IC2C) {
        __syncthreads();
        for (int idx = tid; idx < 324 * IC2C; idx += 256) {
            int icl = idx % IC2C;
            int sp  = idx / IC2C;
            int rr = sp / 18, cc = sp % 18;
            int gh = h0 + rr - 1, gw = w0 + cc - 1;
            float v = 0.f;
            if ((unsigned)gh < 256u && (unsigned)gw < 256u)
                v = cin[((size_t)(b * HW + gh * 256 + gw)) * C1D + ic0 + icl];
            sIn[sp * 21 + icl] = v;
        }
        for (int idx = tid; idx < IC2C * 540; idx += 256) {
            int k   = idx % 9;
            int ocl = (idx / 9) % 60;
            int icl = idx / 540;
            sW[icl * 540 + ocl * 9 + k] =
                w2[((size_t)((ocg * 60 + ocl) * C1D + ic0 + icl)) * 9 + k];
        }
        __syncthreads();
        for (int icl = 0; icl < IC2C; icl++) {
            float xr[3][6];
#pragma unroll
            for (int dr = 0; dr < 3; dr++)
#pragma unroll
                for (int cc = 0; cc < 6; cc++)
                    xr[dr][cc] = sIn[((r + dr) * 18 + c0 + cc) * 21 + icl];
#pragma unroll
            for (int o = 0; o < 15; o++) {
                const float* wp = &sW[icl * 540 + (og * 15 + o) * 9];
                float wv[9];
#pragma unroll
                for (int k = 0; k < 9; k++) wv[k] = wp[k];
#pragma unroll
                for (int dr = 0; dr < 3; dr++)
#pragma unroll
                    for (int dc = 0; dc < 3; dc++)
#pragma unroll
                        for (int p = 0; p < 4; p++)
                            acc[o][p] += xr[dr][p + dc] * wv[dr * 3 + dc];
            }
        }
    }
    __syncthreads();
    float* sOut = smf;
#pragma unroll
    for (int o = 0; o < 15; o++) {
        int ocl = og * 15 + o;
        float bv = b2[ocg * 60 + ocl];
#pragma unroll
        for (int p = 0; p < 4; p++)
            sOut[(r * 16 + c0 + p) * 61 + ocl] = acc[o][p] + bv;
    }
    __syncthreads();
    for (int idx = tid; idx < 256 * 60; idx += 256) {
        int px = idx / 60, oc = idx % 60;
        int gh = h0 + (px >> 4), gw = w0 + (px & 15);
        out[((size_t)(b * HW + gh * 256 + gw)) * CC + ocg * 60 + oc] = sOut[px * 61 + oc];
    }
}

// ---------------- channel pooling (stage 1) ----------------
__global__ __launch_bounds__(256)
void pool_partial_kernel(const float* __restrict__ y, float* __restrict__ pp) {
    __shared__ float s[64 * CC];
    int tid = threadIdx.x;
    int blk = blockIdx.x;
    size_t base = (size_t)blk * 256 * CC;
    float acc = 0.f;
    for (int it = 0; it < 4; it++) {
        __syncthreads();
        const float4* src = (const float4*)(y + base + (size_t)it * 64 * CC);
        float4* d4 = (float4*)s;
        for (int i = tid; i < 64 * CC / 4; i += 256) d4[i] = src[i];
        __syncthreads();
        if (tid < CC) {
#pragma unroll
            for (int t = 0; t < 64; t++) acc += s[t * CC + tid];
        }
    }
    if (tid < CC) pp[blk * CC + tid] = acc;
}

// ---------------- channel attention ----------------
__global__ void ca_kernel(const float* __restrict__ poolp,
                          const float* __restrict__ w1, const float* __restrict__ b1,
                          const float* __restrict__ w2, const float* __restrict__ b2,
                          float* __restrict__ ga) {
    int b = blockIdx.x;
    int t = threadIdx.x;
    __shared__ float mean[CC];
    __shared__ float sq[CAD];
    if (t < CC) {
        float a = 0.f;
        for (int k = 0; k < 256; k++) a += poolp[(size_t)(b * 256 + k) * CC + t];
        mean[t] = a * (1.f / 65536.f);
    }
    __syncthreads();
    if (t < CAD) {
        float a = b1[t];
        for (int c = 0; c < CC; c++) a += mean[c] * w1[t * CC + c];
        sq[t] = fmaxf(a, 0.f);
    }
    __syncthreads();
    if (t < CC) {
        float a = b2[t];
#pragma unroll
        for (int j = 0; j < CAD; j++) a += sq[j] * w2[t * CAD + j];
        ga[b * CC + t] = 0.01f / (1.f + expf(-a));
    }
}

// ---------------- window attention (QKV precomputed, bf16 hi/lo out) ----------------
__global__ __launch_bounds__(256)
void attn_kernel(const float* __restrict__ qkv, const float* __restrict__ bias_table,
                 const int* __restrict__ rpi,
                 __nv_bfloat16* __restrict__ atth, __nv_bfloat16* __restrict__ attl) {
    extern __shared__ float smf[];
    float* sQ = smf;
    float* sK = sQ + 64 * 33;
    float* sV = sK + 64 * 33;
    float* sA = sV + 64 * 33;
    int*   sR = (int*)(sA + 64 * 66);

    const int tid = threadIdx.x;
    const int b   = blockIdx.x >> 10;
    const int win = blockIdx.x & 1023;
    const int wr  = win >> 5, wc = win & 31;
    const int row0 = b * HW + (wr * 8) * 256 + wc * 8;

    for (int idx = tid; idx < 4096; idx += 256) sR[idx] = rpi[idx];

    const float scale = 0.18257418583505536f;
    for (int h = 0; h < HEADS; h++) {
        __syncthreads();
        for (int idx = tid; idx < 1920; idx += 256) {
            int i = idx / 30, d = idx % 30;
            int gt = row0 + (i >> 3) * 256 + (i & 7);
            const float* p = qkv + (size_t)gt * 540 + h * HD + d;
            sQ[i * 33 + d] = p[0] * scale;
            sK[i * 33 + d] = p[180];
            sV[i * 33 + d] = p[360];
        }
        __syncthreads();
        for (int idx = tid; idx < 2048; idx += 256) {
            int j = idx & 63, ip = idx >> 6;
            int i0 = ip * 2, i1 = i0 + 1;
            float s0 = bias_table[sR[i0 * 64 + j] * HEADS + h];
            float s1 = bias_table[sR[i1 * 64 + j] * HEADS + h];
            const float* q0 = sQ + i0 * 33;
            const float* q1 = sQ + i1 * 33;
            const float* kp = sK + j * 33;
#pragma unroll
            for (int d = 0; d < HD; d++) {
                float kv = kp[d];
                s0 += q0[d] * kv; s1 += q1[d] * kv;
            }
            sA[i0 * 66 + j] = s0; sA[i1 * 66 + j] = s1;
        }
        __syncthreads();
        {
            int w = tid >> 5, lane = tid & 31;
            for (int rrow = w; rrow < 64; rrow += 8) {
                float* row = sA + rrow * 66;
                float v0 = row[lane], v1 = row[lane + 32];
                float m = fmaxf(v0, v1);
#pragma unroll
                for (int o = 16; o > 0; o >>= 1) m = fmaxf(m, __shfl_xor_sync(0xffffffffu, m, o));
                float e0 = expf(v0 - m), e1 = expf(v1 - m);
                float s = e0 + e1;
#pragma unroll
                for (int o = 16; o > 0; o >>= 1) s += __shfl_xor_sync(0xffffffffu, s, o);
                float inv = 1.f / s;
                row[lane] = e0 * inv; row[lane + 32] = e1 * inv;
            }
        }
        __syncthreads();
        for (int idx = tid; idx < 960; idx += 256) {
            int d = idx % 30, ip = idx / 30;
            int i0 = ip * 2, i1 = i0 + 1;
            const float* a0 = sA + i0 * 66;
            const float* a1 = sA + i1 * 66;
            float o0 = 0.f, o1 = 0.f;
#pragma unroll 8
            for (int j = 0; j < 64; j++) {
                float vv = sV[j * 33 + d];
                o0 += a0[j] * vv; o1 += a1[j] * vv;
            }
            int gt0 = row0 + (i0 >> 3) * 256 + (i0 & 7);
            int gt1 = row0 + (i1 >> 3) * 256 + (i1 & 7);
            size_t p0 = (size_t)gt0 * CC + h * HD + d;
            size_t p1 = (size_t)gt1 * CC + h * HD + d;
            __nv_bfloat16 hh, ll;
            split2(o0, hh, ll); atth[p0] = hh; attl[p0] = ll;
            split2(o1, hh, ll); atth[p1] = hh; attl[p1] = ll;
        }
    }
}

// ---------------- host launch ----------------
extern "C" void kernel_launch(void* const* d_in, const int* in_sizes, int n_in,
                              void* d_out, int out_size) {
    const float* x          = (const float*)d_in[0];
    const float* ln1_g      = (const float*)d_in[1];
    const float* ln1_b      = (const float*)d_in[2];
    const float* qkv_w      = (const float*)d_in[3];
    const float* qkv_b      = (const float*)d_in[4];
    const float* bias_table = (const float*)d_in[5];
    const float* proj_w     = (const float*)d_in[6];
    const float* proj_b     = (const float*)d_in[7];
    const float* cab_w1     = (const float*)d_in[8];
    const float* cab_b1     = (const float*)d_in[9];
    const float* cab_w2     = (const float*)d_in[10];
    const float* cab_b2     = (const float*)d_in[11];
    const float* ca_w1      = (const float*)d_in[12];
    const float* ca_b1      = (const float*)d_in[13];
    const float* ca_w2      = (const float*)d_in[14];
    const float* ca_b2      = (const float*)d_in[15];
    const float* ln2_g      = (const float*)d_in[16];
    const float* ln2_b      = (const float*)d_in[17];
    const float* fc1_w      = (const float*)d_in[18];
    const float* fc1_b      = (const float*)d_in[19];
    const float* fc2_w      = (const float*)d_in[20];
    const float* fc2_b      = (const float*)d_in[21];
    const int*   rpi        = (const int*)d_in[22];
    float* out = (float*)d_out;

    float *p_xn, *p_qkv, *p_c1, *p_y, *p_xmid, *p_poolp, *p_a;
    __nv_bfloat16 *p_xnh, *p_xnl, *p_atth, *p_attl, *p_hh, *p_hl;
    __nv_bfloat16 *p_wqh, *p_wql, *p_wph, *p_wpl, *p_wf1h, *p_wf1l, *p_wf2h, *p_wf2l;
    cudaGetSymbolAddress((void**)&p_xn,    g_xn);
    cudaGetSymbolAddress((void**)&p_qkv,   g_qkv);
    cudaGetSymbolAddress((void**)&p_c1,    g_c1);
    cudaGetSymbolAddress((void**)&p_y,     g_y);
    cudaGetSymbolAddress((void**)&p_xmid,  g_xmid);
    cudaGetSymbolAddress((void**)&p_poolp, g_poolp);
    cudaGetSymbolAddress((void**)&p_a,     g_a);
    cudaGetSymbolAddress((void**)&p_xnh,   g_xnh);
    cudaGetSymbolAddress((void**)&p_xnl,   g_xnl);
    cudaGetSymbolAddress((void**)&p_atth,  g_atth);
    cudaGetSymbolAddress((void**)&p_attl,  g_attl);
    cudaGetSymbolAddress((void**)&p_hh,    g_hh);
    cudaGetSymbolAddress((void**)&p_hl,    g_hl);
    cudaGetSymbolAddress((void**)&p_wqh,   g_wqh);
    cudaGetSymbolAddress((void**)&p_wql,   g_wql);
    cudaGetSymbolAddress((void**)&p_wph,   g_wph);
    cudaGetSymbolAddress((void**)&p_wpl,   g_wpl);
    cudaGetSymbolAddress((void**)&p_wf1h,  g_wf1h);
    cudaGetSymbolAddress((void**)&p_wf1l,  g_wf1l);
    cudaGetSymbolAddress((void**)&p_wf2h,  g_wf2h);
    cudaGetSymbolAddress((void**)&p_wf2l,  g_wf2l);

    const int smem_conv = (324 * 21 + 20 * 540) * 4;
    const int smem_attn = (3 * 64 * 33 + 64 * 66) * 4 + 4096 * 4;

    cudaFuncSetAttribute(conv1_kernel, cudaFuncAttributeMaxDynamicSharedMemorySize, smem_conv);
    cudaFuncSetAttribute(conv2_kernel, cudaFuncAttributeMaxDynamicSharedMemorySize, smem_conv);
    cudaFuncSetAttribute(attn_kernel,  cudaFuncAttributeMaxDynamicSharedMemorySize, smem_attn);
    cudaFuncSetAttribute(mma_gemm<0>, cudaFuncAttributeMaxDynamicSharedMemorySize, SMEM_MMA);
    cudaFuncSetAttribute(mma_gemm<1>, cudaFuncAttributeMaxDynamicSharedMemorySize, SMEM_MMA);
    cudaFuncSetAttribute(mma_gemm<2>, cudaFuncAttributeMaxDynamicSharedMemorySize, SMEM_MMA);
    cudaFuncSetAttribute(mma_gemm<3>, cudaFuncAttributeMaxDynamicSharedMemorySize, SMEM_MMA);

    // 0. weight splits
    split_kernel<<<(540*CC + 255) / 256, 256>>>(qkv_w, p_wqh, p_wql, 540*CC);
    split_kernel<<<(CC*CC  + 255) / 256, 256>>>(proj_w, p_wph, p_wpl, CC*CC);
    split_kernel<<<(FF*CC  + 255) / 256, 256>>>(fc1_w, p_wf1h, p_wf1l, FF*CC);
    split_kernel<<<(CC*FF  + 255) / 256, 256>>>(fc2_w, p_wf2h, p_wf2l, CC*FF);

    // 1. LN1
    ln_kernel<<<NTOK / 8, 256>>>(x, ln1_g, ln1_b, p_xn, p_xnh, p_xnl, NTOK);
    // 2. conv branch
    conv1_kernel<<<dim3(16, 16, BATCH), 256, smem_conv>>>(p_xn, cab_w1, cab_b1, p_c1);
    conv2_kernel<<<dim3(16, 16, BATCH * 3), 256, smem_conv>>>(p_c1, cab_w2, cab_b2, p_y);
    pool_partial_kernel<<<1024, 256>>>(p_y, p_poolp);
    ca_kernel<<<BATCH, 192>>>(p_poolp, ca_w1, ca_b1, ca_w2, ca_b2, p_a);
    // 3. QKV GEMM + window attention
    mma_gemm<0><<<dim3(9, 2048), 256, SMEM_MMA>>>(p_xnh, p_xnl, p_wqh, p_wql, qkv_b,
                                                  nullptr, nullptr, nullptr,
                                                  p_qkv, nullptr, nullptr, 540, CC);
    attn_kernel<<<NWIN, 256, smem_attn>>>(p_qkv, bias_table, rpi, p_atth, p_attl);
    // 4. proj + residual + conv add
    mma_gemm<2><<<dim3(3, 2048), 256, SMEM_MMA>>>(p_atth, p_attl, p_wph, p_wpl, proj_b,
                                                  x, p_y, p_a,
                                                  p_xmid, nullptr, nullptr, CC, CC);
    // 5. MLP
    ln_kernel<<<NTOK / 8, 256>>>(p_xmid, ln2_g, ln2_b, p_xn, p_xnh, p_xnl, NTOK);
    mma_gemm<1><<<dim3(12, 2048), 256, SMEM_MMA>>>(p_xnh, p_xnl, p_wf1h, p_wf1l, fc1_b,
                                                   nullptr, nullptr, nullptr,
                                                   nullptr, p_hh, p_hl, FF, CC);
    mma_gemm<3><<<dim3(3, 2048), 256, SMEM_MMA>>>(p_hh, p_hl, p_wf2h, p_wf2l, fc2_b,
                                                  p_xmid, nullptr, nullptr,
                                                  out, nullptr, nullptr, CC, FF);
}

// round 10
// speedup vs baseline: 8.7722x; 1.2840x over previous
#include <cuda_runtime.h>
#include <cuda_bf16.h>
#include <math.h>
#include <stdint.h>

// ---------------- Problem constants ----------------
#define BATCH   4
#define HW      65536
#define CC      180
#define C1D     60
#define CAD     6
#define FF      720
#define HEADS   6
#define HD      30
#define NTOK    262144
#define NWIN    4096

// ---------------- Scratch ----------------
__device__ float g_qkv [(size_t)NTOK * 540];
__device__ float g_y   [NTOK * CC];
__device__ float g_xmid[NTOK * CC];
__device__ float g_poolp[1024 * CC];
__device__ float g_a   [BATCH * CC];

__device__ __nv_bfloat16 g_xnh[NTOK * CC],  g_xnl[NTOK * CC];
__device__ __nv_bfloat16 g_c1h[NTOK * C1D], g_c1l[NTOK * C1D];
__device__ __nv_bfloat16 g_atth[NTOK * CC], g_attl[NTOK * CC];
__device__ __nv_bfloat16 g_hh[(size_t)NTOK * FF], g_hl[(size_t)NTOK * FF];
__device__ __nv_bfloat16 g_wqh[540*CC],  g_wql[540*CC];
__device__ __nv_bfloat16 g_wph[CC*CC],   g_wpl[CC*CC];
__device__ __nv_bfloat16 g_wf1h[FF*CC],  g_wf1l[FF*CC];
__device__ __nv_bfloat16 g_wf2h[CC*FF],  g_wf2l[CC*FF];
__device__ __nv_bfloat16 g_w1th[9*C1D*CC], g_w1tl[9*C1D*CC];   // [tap][oc][ic]
__device__ __nv_bfloat16 g_w2th[9*CC*C1D], g_w2tl[9*CC*C1D];   // [tap][oc][ic]

__device__ __forceinline__ float gelu_f(float x) {
    return 0.5f * x * (1.0f + erff(x * 0.70710678118654752f));
}
__device__ __forceinline__ void split2(float f, __nv_bfloat16& h, __nv_bfloat16& l) {
    h = __float2bfloat16(f);
    l = __float2bfloat16(f - __bfloat162float(h));
}
__device__ __forceinline__ uint32_t smem_u32(const void* p) {
    uint32_t a;
    asm("{ .reg .u64 t; cvta.to.shared.u64 t, %1; cvt.u32.u64 %0, t; }" : "=r"(a) : "l"(p));
    return a;
}
__device__ __forceinline__ void ldsm_x4(uint32_t* r, uint32_t addr) {
    asm volatile("ldmatrix.sync.aligned.m8n8.x4.shared.b16 {%0,%1,%2,%3}, [%4];"
        : "=r"(r[0]), "=r"(r[1]), "=r"(r[2]), "=r"(r[3]) : "r"(addr));
}
__device__ __forceinline__ void mma16816(float* c, const uint32_t* a, const uint32_t* b) {
    asm volatile("mma.sync.aligned.m16n8k16.row.col.f32.bf16.bf16.f32 "
        "{%0,%1,%2,%3}, {%4,%5,%6,%7}, {%8,%9}, {%0,%1,%2,%3};"
        : "+f"(c[0]), "+f"(c[1]), "+f"(c[2]), "+f"(c[3])
        : "r"(a[0]), "r"(a[1]), "r"(a[2]), "r"(a[3]), "r"(b[0]), "r"(b[1]));
}

// ---------------- weight split prep ----------------
__global__ void split_kernel(const float* __restrict__ src, __nv_bfloat16* __restrict__ hi,
                             __nv_bfloat16* __restrict__ lo, int n) {
    int i = blockIdx.x * 256 + threadIdx.x;
    if (i < n) { __nv_bfloat16 h, l; split2(src[i], h, l); hi[i] = h; lo[i] = l; }
}
// conv weight: src[oc][ic][3][3] -> dst[tap][oc][ic] hi/lo
__global__ void splitw_conv(const float* __restrict__ src, __nv_bfloat16* __restrict__ hi,
                            __nv_bfloat16* __restrict__ lo, int OC, int IC) {
    int i = blockIdx.x * 256 + threadIdx.x;
    int n = OC * IC * 9;
    if (i < n) {
        int tap = i % 9;
        int ic  = (i / 9) % IC;
        int oc  = i / (9 * IC);
        __nv_bfloat16 h, l; split2(src[i], h, l);
        size_t o = (size_t)tap * OC * IC + (size_t)oc * IC + ic;
        hi[o] = h; lo[o] = l;
    }
}

// ---------------- LayerNorm: bf16 hi/lo (+optional fp32) ----------------
__global__ void ln_kernel(const float* __restrict__ in, const float* __restrict__ g,
                          const float* __restrict__ bt, float* __restrict__ out,
                          __nv_bfloat16* __restrict__ oh, __nv_bfloat16* __restrict__ ol,
                          int ntok) {
    int gwarp = (blockIdx.x * blockDim.x + threadIdx.x) >> 5;
    int lane  = threadIdx.x & 31;
    if (gwarp >= ntok) return;
    const float* p = in + (size_t)gwarp * CC;
    float v[6]; float s = 0.f, s2 = 0.f;
#pragma unroll
    for (int k = 0; k < 6; k++) {
        int c = lane + 32 * k;
        float xv = (c < CC) ? p[c] : 0.f;
        v[k] = xv; s += xv; s2 += xv * xv;
    }
#pragma unroll
    for (int o = 16; o > 0; o >>= 1) {
        s  += __shfl_xor_sync(0xffffffffu, s,  o);
        s2 += __shfl_xor_sync(0xffffffffu, s2, o);
    }
    float mean = s * (1.f / CC);
    float var  = s2 * (1.f / CC) - mean * mean;
    float inv  = rsqrtf(var + 1e-5f);
    size_t base = (size_t)gwarp * CC;
#pragma unroll
    for (int k = 0; k < 6; k++) {
        int c = lane + 32 * k;
        if (c < CC) {
            float y = (v[k] - mean) * inv * g[c] + bt[c];
            if (out) out[base + c] = y;
            __nv_bfloat16 h, l; split2(y, h, l);
            oh[base + c] = h; ol[base + c] = l;
        }
    }
}

// ---------------- shared tile geometry ----------------
#define LDT 72
#define SM_AH 0
#define SM_AL (128 * LDT)
#define SM_BH (2 * 128 * LDT)
#define SM_BL (2 * 128 * LDT + 64 * LDT)
#define SMEM_MMA ((2 * 128 * LDT + 2 * 64 * LDT) * 2)   // 55296 B

// ---------------- bf16 mma.sync GEMM with hi/lo split ----------------
// MODE 0: fp32 +bias | 1: gelu(+bias)->bf16 hi/lo | 2: proj epi | 3: fc2 epi
template<int MODE>
__global__ __launch_bounds__(256)
void mma_gemm(const __nv_bfloat16* __restrict__ Ah, const __nv_bfloat16* __restrict__ Al,
              const __nv_bfloat16* __restrict__ Bh, const __nv_bfloat16* __restrict__ Bl,
              const float* __restrict__ bias,
              const float* __restrict__ aux1, const float* __restrict__ aux2,
              const float* __restrict__ ga,
              float* __restrict__ outf, __nv_bfloat16* __restrict__ outh,
              __nv_bfloat16* __restrict__ outl, int N, int K)
{
    extern __shared__ __nv_bfloat16 sm[];
    __nv_bfloat16* sAh = sm + SM_AH;
    __nv_bfloat16* sAl = sm + SM_AL;
    __nv_bfloat16* sBh = sm + SM_BH;
    __nv_bfloat16* sBl = sm + SM_BL;

    const int tid  = threadIdx.x;
    const int warp = tid >> 5, lane = tid & 31;
    const int wm = warp >> 1, wn = warp & 1;
    const size_t m0 = (size_t)blockIdx.y * 128;
    const int n0 = blockIdx.x * 64;

    float acc[2][4][4];
#pragma unroll
    for (int i = 0; i < 2; i++)
#pragma unroll
        for (int j = 0; j < 4; j++)
#pragma unroll
            for (int c = 0; c < 4; c++) acc[i][j][c] = 0.f;

    const int aRow = (lane & 15), aColOff = (lane >> 4) << 3;
    const int bRow = ((lane >> 4) << 3) + (lane & 7), bColOff = ((lane >> 3) & 1) << 3;

    const int nch = (K + 63) / 64;
    for (int kc = 0; kc < nch; kc++) {
        const int kbase = kc * 64;
        for (int i = tid; i < 128 * 32; i += 256) {
            int row = i >> 5, kp = i & 31;
            int k = kbase + kp * 2;
            uint32_t vh = 0, vl = 0;
            if (k < K) {
                size_t off = (m0 + row) * (size_t)K + k;
                vh = *(const uint32_t*)(Ah + off);
                vl = *(const uint32_t*)(Al + off);
            }
            *(uint32_t*)(sAh + row * LDT + kp * 2) = vh;
            *(uint32_t*)(sAl + row * LDT + kp * 2) = vl;
        }
        for (int i = tid; i < 64 * 32; i += 256) {
            int row = i >> 5, kp = i & 31;
            int k = kbase + kp * 2;
            uint32_t vh = 0, vl = 0;
            if (k < K && n0 + row < N) {
                size_t off = (size_t)(n0 + row) * K + k;
                vh = *(const uint32_t*)(Bh + off);
                vl = *(const uint32_t*)(Bl + off);
            }
            *(uint32_t*)(sBh + row * LDT + kp * 2) = vh;
            *(uint32_t*)(sBl + row * LDT + kp * 2) = vl;
        }
        __syncthreads();

#pragma unroll
        for (int ks = 0; ks < 4; ks++) {
            const int kb = ks * 16;
            uint32_t aH[2][4], aL[2][4], bH[4][2], bL[4][2];
#pragma unroll
            for (int mi = 0; mi < 2; mi++) {
                int r = wm * 32 + mi * 16 + aRow;
                uint32_t adr = smem_u32(sAh + r * LDT + kb + aColOff);
                ldsm_x4(aH[mi], adr);
                ldsm_x4(aL[mi], adr + (SM_AL - SM_AH) * 2);
            }
#pragma unroll
            for (int nf = 0; nf < 2; nf++) {
                int r = wn * 32 + nf * 16 + bRow;
                uint32_t adr = smem_u32(sBh + r * LDT + kb + bColOff);
                uint32_t t[4];
                ldsm_x4(t, adr);
                bH[nf*2][0] = t[0]; bH[nf*2][1] = t[1];
                bH[nf*2+1][0] = t[2]; bH[nf*2+1][1] = t[3];
                ldsm_x4(t, adr + (SM_BL - SM_BH) * 2);
                bL[nf*2][0] = t[0]; bL[nf*2][1] = t[1];
                bL[nf*2+1][0] = t[2]; bL[nf*2+1][1] = t[3];
            }
#pragma unroll
            for (int mi = 0; mi < 2; mi++)
#pragma unroll
                for (int ni = 0; ni < 4; ni++) {
                    mma16816(acc[mi][ni], aH[mi], bH[ni]);
                    mma16816(acc[mi][ni], aH[mi], bL[ni]);
                    mma16816(acc[mi][ni], aL[mi], bH[ni]);
                }
        }
        __syncthreads();
    }

#pragma unroll
    for (int mi = 0; mi < 2; mi++)
#pragma unroll
        for (int hh = 0; hh < 2; hh++) {
            size_t row = m0 + wm * 32 + mi * 16 + (lane >> 2) + hh * 8;
            int bb = (int)(row >> 16);
#pragma unroll
            for (int ni = 0; ni < 4; ni++) {
                int n_ = n0 + wn * 32 + ni * 8 + (lane & 3) * 2;
                if (n_ >= N) continue;
                float v0 = acc[mi][ni][hh * 2 + 0] + bias[n_];
                float v1 = acc[mi][ni][hh * 2 + 1] + bias[n_ + 1];
                size_t o = row * (size_t)N + n_;
                if (MODE == 0) {
                    *(float2*)(outf + o) = make_float2(v0, v1);
                } else if (MODE == 1) {
                    float gg0 = gelu_f(v0), gg1 = gelu_f(v1);
                    __nv_bfloat16 h0, l0, h1, l1;
                    split2(gg0, h0, l0); split2(gg1, h1, l1);
                    __nv_bfloat162 hp; hp.x = h0; hp.y = h1;
                    __nv_bfloat162 lp; lp.x = l0; lp.y = l1;
                    *(__nv_bfloat162*)(outh + o) = hp;
                    *(__nv_bfloat162*)(outl + o) = lp;
                } else if (MODE == 2) {
                    float2 xv = *(const float2*)(aux1 + o);
                    float2 yv = *(const float2*)(aux2 + o);
                    *(float2*)(outf + o) = make_float2(
                        xv.x + v0 + yv.x * ga[bb * CC + n_],
                        xv.y + v1 + yv.y * ga[bb * CC + n_ + 1]);
                } else {
                    float2 xm = *(const float2*)(aux1 + o);
                    *(float2*)(outf + o) = make_float2(xm.x + v0, xm.y + v1);
                }
            }
        }
}

// ---------------- implicit-GEMM 3x3 conv on mma.sync ----------------
// out[tok, oc] = sum_tap x_shift[tok, :KSRC] @ W[tap][oc0+0..59][:KSRC]^T
// CMODE 0: gelu(+bias) -> bf16 hi/lo (stride OCT) | 1: fp32 +bias (stride OCT)
template<int KSRC, int NCH, int OCT, int CMODE>
__global__ __launch_bounds__(256)
void conv_mma(const __nv_bfloat16* __restrict__ Ah, const __nv_bfloat16* __restrict__ Al,
              const __nv_bfloat16* __restrict__ Wh, const __nv_bfloat16* __restrict__ Wl,
              const float* __restrict__ bias,
              float* __restrict__ outf, __nv_bfloat16* __restrict__ outh,
              __nv_bfloat16* __restrict__ outl)
{
    extern __shared__ __nv_bfloat16 sm[];
    __nv_bfloat16* sAh = sm + SM_AH;
    __nv_bfloat16* sAl = sm + SM_AL;
    __nv_bfloat16* sBh = sm + SM_BH;
    __nv_bfloat16* sBl = sm + SM_BL;

    const int tid  = threadIdx.x;
    const int warp = tid >> 5, lane = tid & 31;
    const int wm = warp >> 1, wn = warp & 1;
    const size_t m0 = (size_t)blockIdx.y * 128;
    const int oc0 = blockIdx.x * 60;

    float acc[2][4][4];
#pragma unroll
    for (int i = 0; i < 2; i++)
#pragma unroll
        for (int j = 0; j < 4; j++)
#pragma unroll
            for (int c = 0; c < 4; c++) acc[i][j][c] = 0.f;

    const int aRow = (lane & 15), aColOff = (lane >> 4) << 3;
    const int bRow = ((lane >> 4) << 3) + (lane & 7), bColOff = ((lane >> 3) & 1) << 3;

    for (int tap = 0; tap < 9; tap++) {
        const int dr = tap / 3 - 1, dc = tap % 3 - 1;
        const int toff = dr * 256 + dc;
#pragma unroll 1
        for (int ch = 0; ch < NCH; ch++) {
            const int kb = ch * 64;
            // stage A (shifted input, boundary-masked)
            for (int i = tid; i < 128 * 32; i += 256) {
                int row = i >> 5, kp = i & 31;
                int t = (int)(m0 + row);
                int hh = (t >> 8) & 255, ww = t & 255;
                int k = kb + kp * 2;
                uint32_t vh = 0, vl = 0;
                if ((unsigned)(hh + dr) < 256u && (unsigned)(ww + dc) < 256u && k < KSRC) {
                    size_t off = (size_t)(t + toff) * KSRC + k;
                    vh = *(const uint32_t*)(Ah + off);
                    vl = *(const uint32_t*)(Al + off);
                }
                *(uint32_t*)(sAh + row * LDT + kp * 2) = vh;
                *(uint32_t*)(sAl + row * LDT + kp * 2) = vl;
            }
            // stage B (weights, [tap][oc][ic] contiguous)
            for (int i = tid; i < 64 * 32; i += 256) {
                int n = i >> 5, kp = i & 31;
                int k = kb + kp * 2;
                uint32_t vh = 0, vl = 0;
                if (n < 60 && k < KSRC) {
                    size_t off = (size_t)tap * OCT * KSRC + (size_t)(oc0 + n) * KSRC + k;
                    vh = *(const uint32_t*)(Wh + off);
                    vl = *(const uint32_t*)(Wl + off);
                }
                *(uint32_t*)(sBh + n * LDT + kp * 2) = vh;
                *(uint32_t*)(sBl + n * LDT + kp * 2) = vl;
            }
            __syncthreads();

#pragma unroll
            for (int ks = 0; ks < 4; ks++) {
                const int kbb = ks * 16;
                uint32_t aH[2][4], aL[2][4], bH[4][2], bL[4][2];
#pragma unroll
                for (int mi = 0; mi < 2; mi++) {
                    int r = wm * 32 + mi * 16 + aRow;
                    uint32_t adr = smem_u32(sAh + r * LDT + kbb + aColOff);
                    ldsm_x4(aH[mi], adr);
                    ldsm_x4(aL[mi], adr + (SM_AL - SM_AH) * 2);
                }
#pragma unroll
                for (int nf = 0; nf < 2; nf++) {
                    int r = wn * 32 + nf * 16 + bRow;
                    uint32_t adr = smem_u32(sBh + r * LDT + kbb + bColOff);
                    uint32_t t4[4];
                    ldsm_x4(t4, adr);
                    bH[nf*2][0] = t4[0]; bH[nf*2][1] = t4[1];
                    bH[nf*2+1][0] = t4[2]; bH[nf*2+1][1] = t4[3];
                    ldsm_x4(t4, adr + (SM_BL - SM_BH) * 2);
                    bL[nf*2][0] = t4[0]; bL[nf*2][1] = t4[1];
                    bL[nf*2+1][0] = t4[2]; bL[nf*2+1][1] = t4[3];
                }
#pragma unroll
                for (int mi = 0; mi < 2; mi++)
#pragma unroll
                    for (int ni = 0; ni < 4; ni++) {
                        mma16816(acc[mi][ni], aH[mi], bH[ni]);
                        mma16816(acc[mi][ni], aH[mi], bL[ni]);
                        mma16816(acc[mi][ni], aL[mi], bH[ni]);
                    }
            }
            __syncthreads();
        }
    }

    // epilogue
#pragma unroll
    for (int mi = 0; mi < 2; mi++)
#pragma unroll
        for (int hh = 0; hh < 2; hh++) {
            size_t row = m0 + wm * 32 + mi * 16 + (lane >> 2) + hh * 8;
#pragma unroll
            for (int ni = 0; ni < 4; ni++) {
                int n_ = wn * 32 + ni * 8 + (lane & 3) * 2;
                if (n_ >= 60) continue;
                int oc = oc0 + n_;
                float v0 = acc[mi][ni][hh * 2 + 0] + bias[oc];
                float v1 = acc[mi][ni][hh * 2 + 1] + bias[oc + 1];
                size_t o = row * (size_t)OCT + oc;
                if (CMODE == 0) {
                    float gg0 = gelu_f(v0), gg1 = gelu_f(v1);
                    __nv_bfloat16 h0, l0, h1, l1;
                    split2(gg0, h0, l0); split2(gg1, h1, l1);
                    __nv_bfloat162 hp; hp.x = h0; hp.y = h1;
                    __nv_bfloat162 lp; lp.x = l0; lp.y = l1;
                    *(__nv_bfloat162*)(outh + o) = hp;
                    *(__nv_bfloat162*)(outl + o) = lp;
                } else {
                    *(float2*)(outf + o) = make_float2(v0, v1);
                }
            }
        }
}

// ---------------- channel pooling (stage 1) ----------------
__global__ __launch_bounds__(256)
void pool_partial_kernel(const float* __restrict__ y, float* __restrict__ pp) {
    __shared__ float s[64 * CC];
    int tid = threadIdx.x;
    int blk = blockIdx.x;
    size_t base = (size_t)blk * 256 * CC;
    float acc = 0.f;
    for (int it = 0; it < 4; it++) {
        __syncthreads();
        const float4* src = (const float4*)(y + base + (size_t)it * 64 * CC);
        float4* d4 = (float4*)s;
        for (int i = tid; i < 64 * CC / 4; i += 256) d4[i] = src[i];
        __syncthreads();
        if (tid < CC) {
#pragma unroll
            for (int t = 0; t < 64; t++) acc += s[t * CC + tid];
        }
    }
    if (tid < CC) pp[blk * CC + tid] = acc;
}

// ---------------- channel attention ----------------
__global__ void ca_kernel(const float* __restrict__ poolp,
                          const float* __restrict__ w1, const float* __restrict__ b1,
                          const float* __restrict__ w2, const float* __restrict__ b2,
                          float* __restrict__ ga) {
    int b = blockIdx.x;
    int t = threadIdx.x;
    __shared__ float mean[CC];
    __shared__ float sq[CAD];
    if (t < CC) {
        float a = 0.f;
        for (int k = 0; k < 256; k++) a += poolp[(size_t)(b * 256 + k) * CC + t];
        mean[t] = a * (1.f / 65536.f);
    }
    __syncthreads();
    if (t < CAD) {
        float a = b1[t];
        for (int c = 0; c < CC; c++) a += mean[c] * w1[t * CC + c];
        sq[t] = fmaxf(a, 0.f);
    }
    __syncthreads();
    if (t < CC) {
        float a = b2[t];
#pragma unroll
        for (int j = 0; j < CAD; j++) a += sq[j] * w2[t * CAD + j];
        ga[b * CC + t] = 0.01f / (1.f + expf(-a));
    }
}

// ---------------- window attention (QKV precomputed, bf16 hi/lo out) ----------------
__global__ __launch_bounds__(256)
void attn_kernel(const float* __restrict__ qkv, const float* __restrict__ bias_table,
                 const int* __restrict__ rpi,
                 __nv_bfloat16* __restrict__ atth, __nv_bfloat16* __restrict__ attl) {
    extern __shared__ float smf[];
    float* sQ = smf;
    float* sK = sQ + 64 * 33;
    float* sV = sK + 64 * 33;
    float* sA = sV + 64 * 33;
    int*   sR = (int*)(sA + 64 * 66);

    const int tid = threadIdx.x;
    const int b   = blockIdx.x >> 10;
    const int win = blockIdx.x & 1023;
    const int wr  = win >> 5, wc = win & 31;
    const int row0 = b * HW + (wr * 8) * 256 + wc * 8;

    for (int idx = tid; idx < 4096; idx += 256) sR[idx] = rpi[idx];

    const float scale = 0.18257418583505536f;
    for (int h = 0; h < HEADS; h++) {
        __syncthreads();
        for (int idx = tid; idx < 1920; idx += 256) {
            int i = idx / 30, d = idx % 30;
            int gt = row0 + (i >> 3) * 256 + (i & 7);
            const float* p = qkv + (size_t)gt * 540 + h * HD + d;
            sQ[i * 33 + d] = p[0] * scale;
            sK[i * 33 + d] = p[180];
            sV[i * 33 + d] = p[360];
        }
        __syncthreads();
        for (int idx = tid; idx < 2048; idx += 256) {
            int j = idx & 63, ip = idx >> 6;
            int i0 = ip * 2, i1 = i0 + 1;
            float s0 = bias_table[sR[i0 * 64 + j] * HEADS + h];
            float s1 = bias_table[sR[i1 * 64 + j] * HEADS + h];
            const float* q0 = sQ + i0 * 33;
            const float* q1 = sQ + i1 * 33;
            const float* kp = sK + j * 33;
#pragma unroll
            for (int d = 0; d < HD; d++) {
                float kv = kp[d];
                s0 += q0[d] * kv; s1 += q1[d] * kv;
            }
            sA[i0 * 66 + j] = s0; sA[i1 * 66 + j] = s1;
        }
        __syncthreads();
        {
            int w = tid >> 5, lane = tid & 31;
            for (int rrow = w; rrow < 64; rrow += 8) {
                float* row = sA + rrow * 66;
                float v0 = row[lane], v1 = row[lane + 32];
                float m = fmaxf(v0, v1);
#pragma unroll
                for (int o = 16; o > 0; o >>= 1) m = fmaxf(m, __shfl_xor_sync(0xffffffffu, m, o));
                float e0 = expf(v0 - m), e1 = expf(v1 - m);
                float s = e0 + e1;
#pragma unroll
                for (int o = 16; o > 0; o >>= 1) s += __shfl_xor_sync(0xffffffffu, s, o);
                float inv = 1.f / s;
                row[lane] = e0 * inv; row[lane + 32] = e1 * inv;
            }
        }
        __syncthreads();
        for (int idx = tid; idx < 960; idx += 256) {
            int d = idx % 30, ip = idx / 30;
            int i0 = ip * 2, i1 = i0 + 1;
            const float* a0 = sA + i0 * 66;
            const float* a1 = sA + i1 * 66;
            float o0 = 0.f, o1 = 0.f;
#pragma unroll 8
            for (int j = 0; j < 64; j++) {
                float vv = sV[j * 33 + d];
                o0 += a0[j] * vv; o1 += a1[j] * vv;
            }
            int gt0 = row0 + (i0 >> 3) * 256 + (i0 & 7);
            int gt1 = row0 + (i1 >> 3) * 256 + (i1 & 7);
            size_t p0 = (size_t)gt0 * CC + h * HD + d;
            size_t p1 = (size_t)gt1 * CC + h * HD + d;
            __nv_bfloat16 hh, ll;
            split2(o0, hh, ll); atth[p0] = hh; attl[p0] = ll;
            split2(o1, hh, ll); atth[p1] = hh; attl[p1] = ll;
        }
    }
}

// ---------------- host launch ----------------
extern "C" void kernel_launch(void* const* d_in, const int* in_sizes, int n_in,
                              void* d_out, int out_size) {
    const float* x          = (const float*)d_in[0];
    const float* ln1_g      = (const float*)d_in[1];
    const float* ln1_b      = (const float*)d_in[2];
    const float* qkv_w      = (const float*)d_in[3];
    const float* qkv_b      = (const float*)d_in[4];
    const float* bias_table = (const float*)d_in[5];
    const float* proj_w     = (const float*)d_in[6];
    const float* proj_b     = (const float*)d_in[7];
    const float* cab_w1     = (const float*)d_in[8];
    const float* cab_b1     = (const float*)d_in[9];
    const float* cab_w2     = (const float*)d_in[10];
    const float* cab_b2     = (const float*)d_in[11];
    const float* ca_w1      = (const float*)d_in[12];
    const float* ca_b1      = (const float*)d_in[13];
    const float* ca_w2      = (const float*)d_in[14];
    const float* ca_b2      = (const float*)d_in[15];
    const float* ln2_g      = (const float*)d_in[16];
    const float* ln2_b      = (const float*)d_in[17];
    const float* fc1_w      = (const float*)d_in[18];
    const float* fc1_b      = (const float*)d_in[19];
    const float* fc2_w      = (const float*)d_in[20];
    const float* fc2_b      = (const float*)d_in[21];
    const int*   rpi        = (const int*)d_in[22];
    float* out = (float*)d_out;

    float *p_qkv, *p_y, *p_xmid, *p_poolp, *p_a;
    __nv_bfloat16 *p_xnh, *p_xnl, *p_c1h, *p_c1l, *p_atth, *p_attl, *p_hh, *p_hl;
    __nv_bfloat16 *p_wqh, *p_wql, *p_wph, *p_wpl, *p_wf1h, *p_wf1l, *p_wf2h, *p_wf2l;
    __nv_bfloat16 *p_w1th, *p_w1tl, *p_w2th, *p_w2tl;
    cudaGetSymbolAddress((void**)&p_qkv,   g_qkv);
    cudaGetSymbolAddress((void**)&p_y,     g_y);
    cudaGetSymbolAddress((void**)&p_xmid,  g_xmid);
    cudaGetSymbolAddress((void**)&p_poolp, g_poolp);
    cudaGetSymbolAddress((void**)&p_a,     g_a);
    cudaGetSymbolAddress((void**)&p_xnh,   g_xnh);
    cudaGetSymbolAddress((void**)&p_xnl,   g_xnl);
    cudaGetSymbolAddress((void**)&p_c1h,   g_c1h);
    cudaGetSymbolAddress((void**)&p_c1l,   g_c1l);
    cudaGetSymbolAddress((void**)&p_atth,  g_atth);
    cudaGetSymbolAddress((void**)&p_attl,  g_attl);
    cudaGetSymbolAddress((void**)&p_hh,    g_hh);
    cudaGetSymbolAddress((void**)&p_hl,    g_hl);
    cudaGetSymbolAddress((void**)&p_wqh,   g_wqh);
    cudaGetSymbolAddress((void**)&p_wql,   g_wql);
    cudaGetSymbolAddress((void**)&p_wph,   g_wph);
    cudaGetSymbolAddress((void**)&p_wpl,   g_wpl);
    cudaGetSymbolAddress((void**)&p_wf1h,  g_wf1h);
    cudaGetSymbolAddress((void**)&p_wf1l,  g_wf1l);
    cudaGetSymbolAddress((void**)&p_wf2h,  g_wf2h);
    cudaGetSymbolAddress((void**)&p_wf2l,  g_wf2l);
    cudaGetSymbolAddress((void**)&p_w1th,  g_w1th);
    cudaGetSymbolAddress((void**)&p_w1tl,  g_w1tl);
    cudaGetSymbolAddress((void**)&p_w2th,  g_w2th);
    cudaGetSymbolAddress((void**)&p_w2tl,  g_w2tl);

    const int smem_attn = (3 * 64 * 33 + 64 * 66) * 4 + 4096 * 4;

    cudaFuncSetAttribute(attn_kernel,  cudaFuncAttributeMaxDynamicSharedMemorySize, smem_attn);
    cudaFuncSetAttribute(mma_gemm<0>, cudaFuncAttributeMaxDynamicSharedMemorySize, SMEM_MMA);
    cudaFuncSetAttribute(mma_gemm<1>, cudaFuncAttributeMaxDynamicSharedMemorySize, SMEM_MMA);
    cudaFuncSetAttribute(mma_gemm<2>, cudaFuncAttributeMaxDynamicSharedMemorySize, SMEM_MMA);
    cudaFuncSetAttribute(mma_gemm<3>, cudaFuncAttributeMaxDynamicSharedMemorySize, SMEM_MMA);
    cudaFuncSetAttribute((conv_mma<CC, 3, C1D, 0>), cudaFuncAttributeMaxDynamicSharedMemorySize, SMEM_MMA);
    cudaFuncSetAttribute((conv_mma<C1D, 1, CC, 1>), cudaFuncAttributeMaxDynamicSharedMemorySize, SMEM_MMA);

    // 0. weight splits
    split_kernel<<<(540*CC + 255) / 256, 256>>>(qkv_w, p_wqh, p_wql, 540*CC);
    split_kernel<<<(CC*CC  + 255) / 256, 256>>>(proj_w, p_wph, p_wpl, CC*CC);
    split_kernel<<<(FF*CC  + 255) / 256, 256>>>(fc1_w, p_wf1h, p_wf1l, FF*CC);
    split_kernel<<<(CC*FF  + 255) / 256, 256>>>(fc2_w, p_wf2h, p_wf2l, CC*FF);
    splitw_conv<<<(9*C1D*CC + 255) / 256, 256>>>(cab_w1, p_w1th, p_w1tl, C1D, CC);
    splitw_conv<<<(9*CC*C1D + 255) / 256, 256>>>(cab_w2, p_w2th, p_w2tl, CC, C1D);

    // 1. LN1 (bf16 hi/lo only)
    ln_kernel<<<NTOK / 8, 256>>>(x, ln1_g, ln1_b, nullptr, p_xnh, p_xnl, NTOK);
    // 2. conv branch (implicit-GEMM on tensor cores)
    conv_mma<CC, 3, C1D, 0><<<dim3(1, 2048), 256, SMEM_MMA>>>(
        p_xnh, p_xnl, p_w1th, p_w1tl, cab_b1, nullptr, p_c1h, p_c1l);
    conv_mma<C1D, 1, CC, 1><<<dim3(3, 2048), 256, SMEM_MMA>>>(
        p_c1h, p_c1l, p_w2th, p_w2tl, cab_b2, p_y, nullptr, nullptr);
    pool_partial_kernel<<<1024, 256>>>(p_y, p_poolp);
    ca_kernel<<<BATCH, 192>>>(p_poolp, ca_w1, ca_b1, ca_w2, ca_b2, p_a);
    // 3. QKV GEMM + window attention
    mma_gemm<0><<<dim3(9, 2048), 256, SMEM_MMA>>>(p_xnh, p_xnl, p_wqh, p_wql, qkv_b,
                                                  nullptr, nullptr, nullptr,
                                                  p_qkv, nullptr, nullptr, 540, CC);
    attn_kernel<<<NWIN, 256, smem_attn>>>(p_qkv, bias_table, rpi, p_atth, p_attl);
    // 4. proj + residual + conv add
    mma_gemm<2><<<dim3(3, 2048), 256, SMEM_MMA>>>(p_atth, p_attl, p_wph, p_wpl, proj_b,
                                                  x, p_y, p_a,
                                                  p_xmid, nullptr, nullptr, CC, CC);
    // 5. MLP
    ln_kernel<<<NTOK / 8, 256>>>(p_xmid, ln2_g, ln2_b, nullptr, p_xnh, p_xnl, NTOK);
    mma_gemm<1><<<dim3(12, 2048), 256, SMEM_MMA>>>(p_xnh, p_xnl, p_wf1h, p_wf1l, fc1_b,
                                                   nullptr, nullptr, nullptr,
                                                   nullptr, p_hh, p_hl, FF, CC);
    mma_gemm<3><<<dim3(3, 2048), 256, SMEM_MMA>>>(p_hh, p_hl, p_wf2h, p_wf2l, fc2_b,
                                                  p_xmid, nullptr, nullptr,
                                                  out, nullptr, nullptr, CC, FF);
}

// round 12
// speedup vs baseline: 9.6505x; 1.1001x over previous
#include <cuda_runtime.h>
#include <cuda_bf16.h>
#include <math.h>
#include <stdint.h>

// ---------------- Problem constants ----------------
#define BATCH   4
#define HW      65536
#define CC      180
#define C1D     60
#define CAD     6
#define FF      720
#define HEADS   6
#define HD      30
#define NTOK    262144
#define NWIN    4096

// ---------------- Scratch ----------------
__device__ float g_qkv [(size_t)NTOK * 540];
__device__ float g_y   [NTOK * CC];
__device__ float g_xmid[NTOK * CC];
__device__ float g_poolp[1024 * CC];
__device__ float g_a   [BATCH * CC];

__device__ __nv_bfloat16 g_xnh[NTOK * CC],  g_xnl[NTOK * CC];
__device__ __nv_bfloat16 g_c1h[NTOK * C1D], g_c1l[NTOK * C1D];
__device__ __nv_bfloat16 g_atth[NTOK * CC], g_attl[NTOK * CC];
__device__ __nv_bfloat16 g_hh[(size_t)NTOK * FF], g_hl[(size_t)NTOK * FF];
__device__ __nv_bfloat16 g_wqh[540*CC],  g_wql[540*CC];
__device__ __nv_bfloat16 g_wph[CC*CC],   g_wpl[CC*CC];
__device__ __nv_bfloat16 g_wf1h[FF*CC],  g_wf1l[FF*CC];
__device__ __nv_bfloat16 g_wf2h[CC*FF],  g_wf2l[CC*FF];
__device__ __nv_bfloat16 g_w1th[9*C1D*CC], g_w1tl[9*C1D*CC];   // [tap][oc][ic]
__device__ __nv_bfloat16 g_w2th[9*CC*C1D], g_w2tl[9*CC*C1D];   // [tap][oc][ic]

__device__ __forceinline__ float gelu_f(float x) {
    return 0.5f * x * (1.0f + erff(x * 0.70710678118654752f));
}
__device__ __forceinline__ void split2(float f, __nv_bfloat16& h, __nv_bfloat16& l) {
    h = __float2bfloat16(f);
    l = __float2bfloat16(f - __bfloat162float(h));
}
__device__ __forceinline__ uint32_t smem_u32(const void* p) {
    uint32_t a;
    asm("{ .reg .u64 t; cvta.to.shared.u64 t, %1; cvt.u32.u64 %0, t; }" : "=r"(a) : "l"(p));
    return a;
}
__device__ __forceinline__ void ldsm_x4(uint32_t* r, uint32_t addr) {
    asm volatile("ldmatrix.sync.aligned.m8n8.x4.shared.b16 {%0,%1,%2,%3}, [%4];"
        : "=r"(r[0]), "=r"(r[1]), "=r"(r[2]), "=r"(r[3]) : "r"(addr));
}
__device__ __forceinline__ void mma16816(float* c, const uint32_t* a, const uint32_t* b) {
    asm volatile("mma.sync.aligned.m16n8k16.row.col.f32.bf16.bf16.f32 "
        "{%0,%1,%2,%3}, {%4,%5,%6,%7}, {%8,%9}, {%0,%1,%2,%3};"
        : "+f"(c[0]), "+f"(c[1]), "+f"(c[2]), "+f"(c[3])
        : "r"(a[0]), "r"(a[1]), "r"(a[2]), "r"(a[3]), "r"(b[0]), "r"(b[1]));
}
__device__ __forceinline__ void cp8(uint32_t saddr, const void* g, uint32_t bytes) {
    asm volatile("cp.async.ca.shared.global [%0], [%1], 8, %2;"
        :: "r"(saddr), "l"(g), "r"(bytes));
}
__device__ __forceinline__ void cp_commit() { asm volatile("cp.async.commit_group;"); }
template<int N> __device__ __forceinline__ void cp_wait() {
    asm volatile("cp.async.wait_group %0;" :: "n"(N));
}

// ---------------- weight split prep ----------------
__global__ void split_kernel(const float* __restrict__ src, __nv_bfloat16* __restrict__ hi,
                             __nv_bfloat16* __restrict__ lo, int n) {
    int i = blockIdx.x * 256 + threadIdx.x;
    if (i < n) { __nv_bfloat16 h, l; split2(src[i], h, l); hi[i] = h; lo[i] = l; }
}
__global__ void splitw_conv(const float* __restrict__ src, __nv_bfloat16* __restrict__ hi,
                            __nv_bfloat16* __restrict__ lo, int OC, int IC) {
    int i = blockIdx.x * 256 + threadIdx.x;
    int n = OC * IC * 9;
    if (i < n) {
        int tap = i % 9;
        int ic  = (i / 9) % IC;
        int oc  = i / (9 * IC);
        __nv_bfloat16 h, l; split2(src[i], h, l);
        size_t o = (size_t)tap * OC * IC + (size_t)oc * IC + ic;
        hi[o] = h; lo[o] = l;
    }
}

// ---------------- LayerNorm: bf16 hi/lo ----------------
__global__ void ln_kernel(const float* __restrict__ in, const float* __restrict__ g,
                          const float* __restrict__ bt,
                          __nv_bfloat16* __restrict__ oh, __nv_bfloat16* __restrict__ ol,
                          int ntok) {
    int gwarp = (blockIdx.x * blockDim.x + threadIdx.x) >> 5;
    int lane  = threadIdx.x & 31;
    if (gwarp >= ntok) return;
    const float* p = in + (size_t)gwarp * CC;
    float v[6]; float s = 0.f, s2 = 0.f;
#pragma unroll
    for (int k = 0; k < 6; k++) {
        int c = lane + 32 * k;
        float xv = (c < CC) ? p[c] : 0.f;
        v[k] = xv; s += xv; s2 += xv * xv;
    }
#pragma unroll
    for (int o = 16; o > 0; o >>= 1) {
        s  += __shfl_xor_sync(0xffffffffu, s,  o);
        s2 += __shfl_xor_sync(0xffffffffu, s2, o);
    }
    float mean = s * (1.f / CC);
    float var  = s2 * (1.f / CC) - mean * mean;
    float inv  = rsqrtf(var + 1e-5f);
    size_t base = (size_t)gwarp * CC;
#pragma unroll
    for (int k = 0; k < 6; k++) {
        int c = lane + 32 * k;
        if (c < CC) {
            float y = (v[k] - mean) * inv * g[c] + bt[c];
            __nv_bfloat16 h, l; split2(y, h, l);
            oh[base + c] = h; ol[base + c] = l;
        }
    }
}

// ---------------- tile geometry (double-buffered) ----------------
#define LDT 72
#define E_AH 0
#define E_AL 9216                 // 128*72
#define E_BH 18432
#define E_BL 23040                // 18432 + 64*72
#define BUF_E 27648               // elems per buffer
#define SMEM_MMA (2 * BUF_E * 2)  // 110592 B

// ---------------- bf16 mma.sync GEMM with hi/lo split, cp.async pipelined ----------------
// MODE 0: fp32 +bias | 1: gelu(+bias)->bf16 hi/lo | 2: proj epi | 3: fc2 epi
template<int MODE>
__global__ __launch_bounds__(256)
void mma_gemm(const __nv_bfloat16* __restrict__ Ah, const __nv_bfloat16* __restrict__ Al,
              const __nv_bfloat16* __restrict__ Bh, const __nv_bfloat16* __restrict__ Bl,
              const float* __restrict__ bias,
              const float* __restrict__ aux1, const float* __restrict__ aux2,
              const float* __restrict__ ga,
              float* __restrict__ outf, __nv_bfloat16* __restrict__ outh,
              __nv_bfloat16* __restrict__ outl, int N, int K)
{
    extern __shared__ __nv_bfloat16 sm[];
    const uint32_t sbase = smem_u32(sm);
    const int tid  = threadIdx.x;
    const int warp = tid >> 5, lane = tid & 31;
    const int wm = warp >> 1, wn = warp & 1;
    const size_t m0 = (size_t)blockIdx.y * 128;
    const int n0 = blockIdx.x * 64;

    float acc[2][4][4];
#pragma unroll
    for (int i = 0; i < 2; i++)
#pragma unroll
        for (int j = 0; j < 4; j++)
#pragma unroll
            for (int c = 0; c < 4; c++) acc[i][j][c] = 0.f;

    const int aRow = (lane & 15), aColOff = (lane >> 4) << 3;
    const int bRow = ((lane >> 4) << 3) + (lane & 7), bColOff = ((lane >> 3) & 1) << 3;
    const int nch = (K + 63) / 64;

#define G_STAGE(buf, kc) do { \
    const int kbase = (kc) * 64; \
    const uint32_t bb = sbase + (uint32_t)(buf) * (BUF_E * 2); \
    for (int i = tid; i < 2048; i += 256) { \
        int row = i >> 4, c = i & 15; \
        int k = kbase + c * 4; \
        int vb = K - k; vb = vb < 0 ? 0 : (vb > 4 ? 4 : vb); \
        size_t off = (m0 + row) * (size_t)K + (vb ? k : 0); \
        uint32_t sa = bb + (uint32_t)(row * LDT + c * 4) * 2; \
        cp8(sa,            Ah + off, (uint32_t)vb * 2); \
        cp8(sa + E_AL * 2, Al + off, (uint32_t)vb * 2); \
    } \
    for (int i = tid; i < 1024; i += 256) { \
        int row = i >> 4, c = i & 15; \
        int k = kbase + c * 4; \
        int vb = K - k; vb = vb < 0 ? 0 : (vb > 4 ? 4 : vb); \
        if (n0 + row >= N) vb = 0; \
        size_t off = (size_t)(n0 + (vb ? row : 0)) * K + (vb ? k : 0); \
        uint32_t sa = bb + (uint32_t)(E_BH + row * LDT + c * 4) * 2; \
        cp8(sa,                    Bh + off, (uint32_t)vb * 2); \
        cp8(sa + (E_BL - E_BH) * 2, Bl + off, (uint32_t)vb * 2); \
    } \
} while (0)

    G_STAGE(0, 0);
    cp_commit();
    for (int kc = 0; kc < nch; kc++) {
        const int cur = kc & 1;
        if (kc + 1 < nch) { G_STAGE(cur ^ 1, kc + 1); cp_commit(); cp_wait<1>(); }
        else cp_wait<0>();
        __syncthreads();

        __nv_bfloat16* bA = sm + cur * BUF_E;
#pragma unroll
        for (int ks = 0; ks < 4; ks++) {
            const int kb = ks * 16;
            uint32_t aH[2][4], aL[2][4], bH[4][2], bL[4][2];
#pragma unroll
            for (int mi = 0; mi < 2; mi++) {
                int r = wm * 32 + mi * 16 + aRow;
                uint32_t adr = smem_u32(bA + r * LDT + kb + aColOff);
                ldsm_x4(aH[mi], adr);
                ldsm_x4(aL[mi], adr + E_AL * 2);
            }
#pragma unroll
            for (int nf = 0; nf < 2; nf++) {
                int r = wn * 32 + nf * 16 + bRow;
                uint32_t adr = smem_u32(bA + E_BH + r * LDT + kb + bColOff);
                uint32_t t[4];
                ldsm_x4(t, adr);
                bH[nf*2][0] = t[0]; bH[nf*2][1] = t[1];
                bH[nf*2+1][0] = t[2]; bH[nf*2+1][1] = t[3];
                ldsm_x4(t, adr + (E_BL - E_BH) * 2);
                bL[nf*2][0] = t[0]; bL[nf*2][1] = t[1];
                bL[nf*2+1][0] = t[2]; bL[nf*2+1][1] = t[3];
            }
#pragma unroll
            for (int mi = 0; mi < 2; mi++)
#pragma unroll
                for (int ni = 0; ni < 4; ni++) {
                    mma16816(acc[mi][ni], aH[mi], bH[ni]);
                    mma16816(acc[mi][ni], aH[mi], bL[ni]);
                    mma16816(acc[mi][ni], aL[mi], bH[ni]);
                }
        }
        __syncthreads();
    }
#undef G_STAGE

#pragma unroll
    for (int mi = 0; mi < 2; mi++)
#pragma unroll
        for (int hh = 0; hh < 2; hh++) {
            size_t row = m0 + wm * 32 + mi * 16 + (lane >> 2) + hh * 8;
            int bb = (int)(row >> 16);
#pragma unroll
            for (int ni = 0; ni < 4; ni++) {
                int n_ = n0 + wn * 32 + ni * 8 + (lane & 3) * 2;
                if (n_ >= N) continue;
                float v0 = acc[mi][ni][hh * 2 + 0] + bias[n_];
                float v1 = acc[mi][ni][hh * 2 + 1] + bias[n_ + 1];
                size_t o = row * (size_t)N + n_;
                if (MODE == 0) {
                    *(float2*)(outf + o) = make_float2(v0, v1);
                } else if (MODE == 1) {
                    float gg0 = gelu_f(v0), gg1 = gelu_f(v1);
                    __nv_bfloat16 h0, l0, h1, l1;
                    split2(gg0, h0, l0); split2(gg1, h1, l1);
                    __nv_bfloat162 hp; hp.x = h0; hp.y = h1;
                    __nv_bfloat162 lp; lp.x = l0; lp.y = l1;
                    *(__nv_bfloat162*)(outh + o) = hp;
                    *(__nv_bfloat162*)(outl + o) = lp;
                } else if (MODE == 2) {
                    float2 xv = *(const float2*)(aux1 + o);
                    float2 yv = *(const float2*)(aux2 + o);
                    *(float2*)(outf + o) = make_float2(
                        xv.x + v0 + yv.x * ga[bb * CC + n_],
                        xv.y + v1 + yv.y * ga[bb * CC + n_ + 1]);
                } else {
                    float2 xm = *(const float2*)(aux1 + o);
                    *(float2*)(outf + o) = make_float2(xm.x + v0, xm.y + v1);
                }
            }
        }
}

// ---------------- implicit-GEMM 3x3 conv, cp.async pipelined ----------------
// CMODE 0: gelu(+bias)->bf16 hi/lo | 1: fp32 +bias
template<int KSRC, int NCH, int OCT, int CMODE>
__global__ __launch_bounds__(256)
void conv_mma(const __nv_bfloat16* __restrict__ Ah, const __nv_bfloat16* __restrict__ Al,
              const __nv_bfloat16* __restrict__ Wh, const __nv_bfloat16* __restrict__ Wl,
              const float* __restrict__ bias,
              float* __restrict__ outf, __nv_bfloat16* __restrict__ outh,
              __nv_bfloat16* __restrict__ outl)
{
    extern __shared__ __nv_bfloat16 sm[];
    const uint32_t sbase = smem_u32(sm);
    const int tid  = threadIdx.x;
    const int warp = tid >> 5, lane = tid & 31;
    const int wm = warp >> 1, wn = warp & 1;
    const size_t m0 = (size_t)blockIdx.y * 128;
    const int oc0 = blockIdx.x * 60;

    float acc[2][4][4];
#pragma unroll
    for (int i = 0; i < 2; i++)
#pragma unroll
        for (int j = 0; j < 4; j++)
#pragma unroll
            for (int c = 0; c < 4; c++) acc[i][j][c] = 0.f;

    const int aRow = (lane & 15), aColOff = (lane >> 4) << 3;
    const int bRow = ((lane >> 4) << 3) + (lane & 7), bColOff = ((lane >> 3) & 1) << 3;
    const int NIT = 9 * NCH;

#define C_STAGE(buf, it) do { \
    const int tap = (it) / NCH; \
    const int kbase = ((it) % NCH) * 64; \
    const int dr = tap / 3 - 1, dc = tap % 3 - 1; \
    const int toff = dr * 256 + dc; \
    const uint32_t bb = sbase + (uint32_t)(buf) * (BUF_E * 2); \
    for (int i = tid; i < 2048; i += 256) { \
        int row = i >> 4, c = i & 15; \
        int t = (int)(m0 + row); \
        int hh2 = (t >> 8) & 255, ww2 = t & 255; \
        int k = kbase + c * 4; \
        int vb = KSRC - k; vb = vb < 0 ? 0 : (vb > 4 ? 4 : vb); \
        if ((unsigned)(hh2 + dr) >= 256u || (unsigned)(ww2 + dc) >= 256u) vb = 0; \
        size_t off = vb ? ((size_t)(t + toff) * KSRC + k) : 0; \
        uint32_t sa = bb + (uint32_t)(row * LDT + c * 4) * 2; \
        cp8(sa,            Ah + off, (uint32_t)vb * 2); \
        cp8(sa + E_AL * 2, Al + off, (uint32_t)vb * 2); \
    } \
    for (int i = tid; i < 1024; i += 256) { \
        int n = i >> 4, c = i & 15; \
        int k = kbase + c * 4; \
        int vb = KSRC - k; vb = vb < 0 ? 0 : (vb > 4 ? 4 : vb); \
        if (n >= 60) vb = 0; \
        size_t off = vb ? ((size_t)tap * OCT * KSRC + (size_t)(oc0 + n) * KSRC + k) : 0; \
        uint32_t sa = bb + (uint32_t)(E_BH + n * LDT + c * 4) * 2; \
        cp8(sa,                     Wh + off, (uint32_t)vb * 2); \
        cp8(sa + (E_BL - E_BH) * 2, Wl + off, (uint32_t)vb * 2); \
    } \
} while (0)

    C_STAGE(0, 0);
    cp_commit();
    for (int it = 0; it < NIT; it++) {
        const int cur = it & 1;
        if (it + 1 < NIT) { C_STAGE(cur ^ 1, it + 1); cp_commit(); cp_wait<1>(); }
        else cp_wait<0>();
        __syncthreads();

        __nv_bfloat16* bA = sm + cur * BUF_E;
#pragma unroll
        for (int ks = 0; ks < 4; ks++) {
            const int kbb = ks * 16;
            uint32_t aH[2][4], aL[2][4], bH[4][2], bL[4][2];
#pragma unroll
            for (int mi = 0; mi < 2; mi++) {
                int r = wm * 32 + mi * 16 + aRow;
                uint32_t adr = smem_u32(bA + r * LDT + kbb + aColOff);
                ldsm_x4(aH[mi], adr);
                ldsm_x4(aL[mi], adr + E_AL * 2);
            }
#pragma unroll
            for (int nf = 0; nf < 2; nf++) {
                int r = wn * 32 + nf * 16 + bRow;
                uint32_t adr = smem_u32(bA + E_BH + r * LDT + kbb + bColOff);
                uint32_t t4[4];
                ldsm_x4(t4, adr);
                bH[nf*2][0] = t4[0]; bH[nf*2][1] = t4[1];
                bH[nf*2+1][0] = t4[2]; bH[nf*2+1][1] = t4[3];
                ldsm_x4(t4, adr + (E_BL - E_BH) * 2);
                bL[nf*2][0] = t4[0]; bL[nf*2][1] = t4[1];
                bL[nf*2+1][0] = t4[2]; bL[nf*2+1][1] = t4[3];
            }
#pragma unroll
            for (int mi = 0; mi < 2; mi++)
#pragma unroll
                for (int ni = 0; ni < 4; ni++) {
                    mma16816(acc[mi][ni], aH[mi], bH[ni]);
                    mma16816(acc[mi][ni], aH[mi], bL[ni]);
                    mma16816(acc[mi][ni], aL[mi], bH[ni]);
                }
        }
        __syncthreads();
    }
#undef C_STAGE

#pragma unroll
    for (int mi = 0; mi < 2; mi++)
#pragma unroll
        for (int hh = 0; hh < 2; hh++) {
            size_t row = m0 + wm * 32 + mi * 16 + (lane >> 2) + hh * 8;
#pragma unroll
            for (int ni = 0; ni < 4; ni++) {
                int n_ = wn * 32 + ni * 8 + (lane & 3) * 2;
                if (n_ >= 60) continue;
                int oc = oc0 + n_;
                float v0 = acc[mi][ni][hh * 2 + 0] + bias[oc];
                float v1 = acc[mi][ni][hh * 2 + 1] + bias[oc + 1];
                size_t o = row * (size_t)OCT + oc;
                if (CMODE == 0) {
                    float gg0 = gelu_f(v0), gg1 = gelu_f(v1);
                    __nv_bfloat16 h0, l0, h1, l1;
                    split2(gg0, h0, l0); split2(gg1, h1, l1);
                    __nv_bfloat162 hp; hp.x = h0; hp.y = h1;
                    __nv_bfloat162 lp; lp.x = l0; lp.y = l1;
                    *(__nv_bfloat162*)(outh + o) = hp;
                    *(__nv_bfloat162*)(outl + o) = lp;
                } else {
                    *(float2*)(outf + o) = make_float2(v0, v1);
                }
            }
        }
}

// ---------------- channel pooling (stage 1) ----------------
__global__ __launch_bounds__(256)
void pool_partial_kernel(const float* __restrict__ y, float* __restrict__ pp) {
    __shared__ float s[64 * CC];
    int tid = threadIdx.x;
    int blk = blockIdx.x;
    size_t base = (size_t)blk * 256 * CC;
    float acc = 0.f;
    for (int it = 0; it < 4; it++) {
        __syncthreads();
        const float4* src = (const float4*)(y + base + (size_t)it * 64 * CC);
        float4* d4 = (float4*)s;
        for (int i = tid; i < 64 * CC / 4; i += 256) d4[i] = src[i];
        __syncthreads();
        if (tid < CC) {
#pragma unroll
            for (int t = 0; t < 64; t++) acc += s[t * CC + tid];
        }
    }
    if (tid < CC) pp[blk * CC + tid] = acc;
}

// ---------------- channel attention ----------------
__global__ void ca_kernel(const float* __restrict__ poolp,
                          const float* __restrict__ w1, const float* __restrict__ b1,
                          const float* __restrict__ w2, const float* __restrict__ b2,
                          float* __restrict__ ga) {
    int b = blockIdx.x;
    int t = threadIdx.x;
    __shared__ float mean[CC];
    __shared__ float sq[CAD];
    if (t < CC) {
        float a = 0.f;
        for (int k = 0; k < 256; k++) a += poolp[(size_t)(b * 256 + k) * CC + t];
        mean[t] = a * (1.f / 65536.f);
    }
    __syncthreads();
    if (t < CAD) {
        float a = b1[t];
        for (int c = 0; c < CC; c++) a += mean[c] * w1[t * CC + c];
        sq[t] = fmaxf(a, 0.f);
    }
    __syncthreads();
    if (t < CC) {
        float a = b2[t];
#pragma unroll
        for (int j = 0; j < CAD; j++) a += sq[j] * w2[t * CAD + j];
        ga[b * CC + t] = 0.01f / (1.f + expf(-a));
    }
}

// ---------------- window attention ----------------
__global__ __launch_bounds__(256)
void attn_kernel(const float* __restrict__ qkv, const float* __restrict__ bias_table,
                 const int* __restrict__ rpi,
                 __nv_bfloat16* __restrict__ atth, __nv_bfloat16* __restrict__ attl) {
    extern __shared__ float smf[];
    float* sQ = smf;
    float* sK = sQ + 64 * 33;
    float* sV = sK + 64 * 33;
    float* sA = sV + 64 * 33;
    int*   sR = (int*)(sA + 64 * 66);

    const int tid = threadIdx.x;
    const int b   = blockIdx.x >> 10;
    const int win = blockIdx.x & 1023;
    const int wr  = win >> 5, wc = win & 31;
    const int row0 = b * HW + (wr * 8) * 256 + wc * 8;

    for (int idx = tid; idx < 4096; idx += 256) sR[idx] = rpi[idx];

    const float scale = 0.18257418583505536f;
    for (int h = 0; h < HEADS; h++) {
        __syncthreads();
        for (int idx = tid; idx < 1920; idx += 256) {
            int i = idx / 30, d = idx % 30;
            int gt = row0 + (i >> 3) * 256 + (i & 7);
            const float* p = qkv + (size_t)gt * 540 + h * HD + d;
            sQ[i * 33 + d] = p[0] * scale;
            sK[i * 33 + d] = p[180];
            sV[i * 33 + d] = p[360];
        }
        __syncthreads();
        for (int idx = tid; idx < 2048; idx += 256) {
            int j = idx & 63, ip = idx >> 6;
            int i0 = ip * 2, i1 = i0 + 1;
            float s0 = bias_table[sR[i0 * 64 + j] * HEADS + h];
            float s1 = bias_table[sR[i1 * 64 + j] * HEADS + h];
            const float* q0 = sQ + i0 * 33;
            const float* q1 = sQ + i1 * 33;
            const float* kp = sK + j * 33;
#pragma unroll
            for (int d = 0; d < HD; d++) {
                float kv = kp[d];
                s0 += q0[d] * kv; s1 += q1[d] * kv;
            }
            sA[i0 * 66 + j] = s0; sA[i1 * 66 + j] = s1;
        }
        __syncthreads();
        {
            int w = tid >> 5, lane = tid & 31;
            for (int rrow = w; rrow < 64; rrow += 8) {
                float* row = sA + rrow * 66;
                float v0 = row[lane], v1 = row[lane + 32];
                float m = fmaxf(v0, v1);
#pragma unroll
                for (int o = 16; o > 0; o >>= 1) m = fmaxf(m, __shfl_xor_sync(0xffffffffu, m, o));
                float e0 = expf(v0 - m), e1 = expf(v1 - m);
                float s = e0 + e1;
#pragma unroll
                for (int o = 16; o > 0; o >>= 1) s += __shfl_xor_sync(0xffffffffu, s, o);
                float inv = 1.f / s;
                row[lane] = e0 * inv; row[lane + 32] = e1 * inv;
            }
        }
        __syncthreads();
        for (int idx = tid; idx < 960; idx += 256) {
            int d = idx % 30, ip = idx / 30;
            int i0 = ip * 2, i1 = i0 + 1;
            const float* a0 = sA + i0 * 66;
            const float* a1 = sA + i1 * 66;
            float o0 = 0.f, o1 = 0.f;
#pragma unroll 8
            for (int j = 0; j < 64; j++) {
                float vv = sV[j * 33 + d];
                o0 += a0[j] * vv; o1 += a1[j] * vv;
            }
            int gt0 = row0 + (i0 >> 3) * 256 + (i0 & 7);
            int gt1 = row0 + (i1 >> 3) * 256 + (i1 & 7);
            size_t p0 = (size_t)gt0 * CC + h * HD + d;
            size_t p1 = (size_t)gt1 * CC + h * HD + d;
            __nv_bfloat16 hh, ll;
            split2(o0, hh, ll); atth[p0] = hh; attl[p0] = ll;
            split2(o1, hh, ll); atth[p1] = hh; attl[p1] = ll;
        }
    }
}

// ---------------- host launch ----------------
extern "C" void kernel_launch(void* const* d_in, const int* in_sizes, int n_in,
                              void* d_out, int out_size) {
    const float* x          = (const float*)d_in[0];
    const float* ln1_g      = (const float*)d_in[1];
    const float* ln1_b      = (const float*)d_in[2];
    const float* qkv_w      = (const float*)d_in[3];
    const float* qkv_b      = (const float*)d_in[4];
    const float* bias_table = (const float*)d_in[5];
    const float* proj_w     = (const float*)d_in[6];
    const float* proj_b     = (const float*)d_in[7];
    const float* cab_w1     = (const float*)d_in[8];
    const float* cab_b1     = (const float*)d_in[9];
    const float* cab_w2     = (const float*)d_in[10];
    const float* cab_b2     = (const float*)d_in[11];
    const float* ca_w1      = (const float*)d_in[12];
    const float* ca_b1      = (const float*)d_in[13];
    const float* ca_w2      = (const float*)d_in[14];
    const float* ca_b2      = (const float*)d_in[15];
    const float* ln2_g      = (const float*)d_in[16];
    const float* ln2_b      = (const float*)d_in[17];
    const float* fc1_w      = (const float*)d_in[18];
    const float* fc1_b      = (const float*)d_in[19];
    const float* fc2_w      = (const float*)d_in[20];
    const float* fc2_b      = (const float*)d_in[21];
    const int*   rpi        = (const int*)d_in[22];
    float* out = (float*)d_out;

    float *p_qkv, *p_y, *p_xmid, *p_poolp, *p_a;
    __nv_bfloat16 *p_xnh, *p_xnl, *p_c1h, *p_c1l, *p_atth, *p_attl, *p_hh, *p_hl;
    __nv_bfloat16 *p_wqh, *p_wql, *p_wph, *p_wpl, *p_wf1h, *p_wf1l, *p_wf2h, *p_wf2l;
    __nv_bfloat16 *p_w1th, *p_w1tl, *p_w2th, *p_w2tl;
    cudaGetSymbolAddress((void**)&p_qkv,   g_qkv);
    cudaGetSymbolAddress((void**)&p_y,     g_y);
    cudaGetSymbolAddress((void**)&p_xmid,  g_xmid);
    cudaGetSymbolAddress((void**)&p_poolp, g_poolp);
    cudaGetSymbolAddress((void**)&p_a,     g_a);
    cudaGetSymbolAddress((void**)&p_xnh,   g_xnh);
    cudaGetSymbolAddress((void**)&p_xnl,   g_xnl);
    cudaGetSymbolAddress((void**)&p_c1h,   g_c1h);
    cudaGetSymbolAddress((void**)&p_c1l,   g_c1l);
    cudaGetSymbolAddress((void**)&p_atth,  g_atth);
    cudaGetSymbolAddress((void**)&p_attl,  g_attl);
    cudaGetSymbolAddress((void**)&p_hh,    g_hh);
    cudaGetSymbolAddress((void**)&p_hl,    g_hl);
    cudaGetSymbolAddress((void**)&p_wqh,   g_wqh);
    cudaGetSymbolAddress((void**)&p_wql,   g_wql);
    cudaGetSymbolAddress((void**)&p_wph,   g_wph);
    cudaGetSymbolAddress((void**)&p_wpl,   g_wpl);
    cudaGetSymbolAddress((void**)&p_wf1h,  g_wf1h);
    cudaGetSymbolAddress((void**)&p_wf1l,  g_wf1l);
    cudaGetSymbolAddress((void**)&p_wf2h,  g_wf2h);
    cudaGetSymbolAddress((void**)&p_wf2l,  g_wf2l);
    cudaGetSymbolAddress((void**)&p_w1th,  g_w1th);
    cudaGetSymbolAddress((void**)&p_w1tl,  g_w1tl);
    cudaGetSymbolAddress((void**)&p_w2th,  g_w2th);
    cudaGetSymbolAddress((void**)&p_w2tl,  g_w2tl);

    const int smem_attn = (3 * 64 * 33 + 64 * 66) * 4 + 4096 * 4;

    cudaFuncSetAttribute(attn_kernel,  cudaFuncAttributeMaxDynamicSharedMemorySize, smem_attn);
    cudaFuncSetAttribute(mma_gemm<0>, cudaFuncAttributeMaxDynamicSharedMemorySize, SMEM_MMA);
    cudaFuncSetAttribute(mma_gemm<1>, cudaFuncAttributeMaxDynamicSharedMemorySize, SMEM_MMA);
    cudaFuncSetAttribute(mma_gemm<2>, cudaFuncAttributeMaxDynamicSharedMemorySize, SMEM_MMA);
    cudaFuncSetAttribute(mma_gemm<3>, cudaFuncAttributeMaxDynamicSharedMemorySize, SMEM_MMA);
    cudaFuncSetAttribute((conv_mma<CC, 3, C1D, 0>), cudaFuncAttributeMaxDynamicSharedMemorySize, SMEM_MMA);
    cudaFuncSetAttribute((conv_mma<C1D, 1, CC, 1>), cudaFuncAttributeMaxDynamicSharedMemorySize, SMEM_MMA);

    // 0. weight splits
    split_kernel<<<(540*CC + 255) / 256, 256>>>(qkv_w, p_wqh, p_wql, 540*CC);
    split_kernel<<<(CC*CC  + 255) / 256, 256>>>(proj_w, p_wph, p_wpl, CC*CC);
    split_kernel<<<(FF*CC  + 255) / 256, 256>>>(fc1_w, p_wf1h, p_wf1l, FF*CC);
    split_kernel<<<(CC*FF  + 255) / 256, 256>>>(fc2_w, p_wf2h, p_wf2l, CC*FF);
    splitw_conv<<<(9*C1D*CC + 255) / 256, 256>>>(cab_w1, p_w1th, p_w1tl, C1D, CC);
    splitw_conv<<<(9*CC*C1D + 255) / 256, 256>>>(cab_w2, p_w2th, p_w2tl, CC, C1D);

    // 1. LN1
    ln_kernel<<<NTOK / 8, 256>>>(x, ln1_g, ln1_b, p_xnh, p_xnl, NTOK);
    // 2. conv branch
    conv_mma<CC, 3, C1D, 0><<<dim3(1, 2048), 256, SMEM_MMA>>>(
        p_xnh, p_xnl, p_w1th, p_w1tl, cab_b1, nullptr, p_c1h, p_c1l);
    conv_mma<C1D, 1, CC, 1><<<dim3(3, 2048), 256, SMEM_MMA>>>(
        p_c1h, p_c1l, p_w2th, p_w2tl, cab_b2, p_y, nullptr, nullptr);
    pool_partial_kernel<<<1024, 256>>>(p_y, p_poolp);
    ca_kernel<<<BATCH, 192>>>(p_poolp, ca_w1, ca_b1, ca_w2, ca_b2, p_a);
    // 3. QKV GEMM + window attention
    mma_gemm<0><<<dim3(9, 2048), 256, SMEM_MMA>>>(p_xnh, p_xnl, p_wqh, p_wql, qkv_b,
                                                  nullptr, nullptr, nullptr,
                                                  p_qkv, nullptr, nullptr, 540, CC);
    attn_kernel<<<NWIN, 256, smem_attn>>>(p_qkv, bias_table, rpi, p_atth, p_attl);
    // 4. proj + residual + conv add
    mma_gemm<2><<<dim3(3, 2048), 256, SMEM_MMA>>>(p_atth, p_attl, p_wph, p_wpl, proj_b,
                                                  x, p_y, p_a,
                                                  p_xmid, nullptr, nullptr, CC, CC);
    // 5. MLP
    ln_kernel<<<NTOK / 8, 256>>>(p_xmid, ln2_g, ln2_b, p_xnh, p_xnl, NTOK);
    mma_gemm<1><<<dim3(12, 2048), 256, SMEM_MMA>>>(p_xnh, p_xnl, p_wf1h, p_wf1l, fc1_b,
                                                   nullptr, nullptr, nullptr,
                                                   nullptr, p_hh, p_hl, FF, CC);
    mma_gemm<3><<<dim3(3, 2048), 256, SMEM_MMA>>>(p_hh, p_hl, p_wf2h, p_wf2l, fc2_b,
                                                  p_xmid, nullptr, nullptr,
                                                  out, nullptr, nullptr, CC, FF);
}